// round 7
// baseline (speedup 1.0000x reference)
#include <cuda_runtime.h>
#include <cuda_bf16.h>
#include <cstdint>

#define BD 2
#define TT 2048
#define CC 2048
#define NH 16
#define HD 128
#define MTOT (BD*TT)
#define BHH (BD*NH)
typedef __nv_bfloat16 bf16;
typedef __nv_bfloat162 bf162;

__device__ bf16 g_xhi[MTOT*CC], g_xlo[MTOT*CC];
__device__ bf16 g_whi[4][CC*CC], g_wlo[4][CC*CC];
__device__ bf16 g_qhi[BHH*TT*HD], g_qlo[BHH*TT*HD];
__device__ bf16 g_khi[BHH*TT*HD], g_klo[BHH*TT*HD];
__device__ bf16 g_vthi[BHH*HD*TT], g_vtlo[BHH*HD*TT];
__device__ bf16 g_yhi[MTOT*CC], g_ylo[MTOT*CC];

// ---- helpers ----
__device__ __forceinline__ uint32_t su32(const void* p){
    uint32_t a; asm("{.reg .u64 t; cvta.to.shared.u64 t,%1; cvt.u32.u64 %0,t;}":"=r"(a):"l"(p)); return a;
}
#define CP_ASYNC16(s,g) asm volatile("cp.async.cg.shared.global [%0], [%1], 16;" ::"r"(s),"l"(g))
#define CP_COMMIT() asm volatile("cp.async.commit_group;" ::: "memory")
#define LDSM4(r0,r1,r2,r3,addr) \
    asm volatile("ldmatrix.sync.aligned.m8n8.x4.shared.b16 {%0,%1,%2,%3},[%4];" \
                 :"=r"(r0),"=r"(r1),"=r"(r2),"=r"(r3):"r"(addr))

__device__ __forceinline__ void mma16816(float* d, const uint32_t* a, const uint32_t* b){
    asm volatile("mma.sync.aligned.m16n8k16.row.col.f32.bf16.bf16.f32 "
        "{%0,%1,%2,%3},{%4,%5,%6,%7},{%8,%9},{%0,%1,%2,%3};"
        : "+f"(d[0]),"+f"(d[1]),"+f"(d[2]),"+f"(d[3])
        : "r"(a[0]),"r"(a[1]),"r"(a[2]),"r"(a[3]),"r"(b[0]),"r"(b[1]));
}

__device__ __forceinline__ void split1(float v, bf16& h, bf16& l){
    h = __float2bfloat16(v); l = __float2bfloat16(v - __bfloat162float(h));
}
__device__ __forceinline__ uint32_t pack_hi(float x, float y){
    bf162 t = __halves2bfloat162(__float2bfloat16(x), __float2bfloat16(y));
    return *(uint32_t*)&t;
}
__device__ __forceinline__ uint32_t pack_lo(float x, float y){
    bf16 hx,lx,hy,ly; split1(x,hx,lx); split1(y,hy,ly);
    bf162 t = __halves2bfloat162(lx,ly);
    return *(uint32_t*)&t;
}

// ---- split fp32 -> bf16 hi/lo ----
template<int DST>
__global__ __launch_bounds__(256) void split_k(const float* __restrict__ s){
    bf16 *Hi, *Lo;
    if (DST==0){Hi=g_xhi;Lo=g_xlo;} else {Hi=g_whi[DST-1];Lo=g_wlo[DST-1];}
    int i = blockIdx.x*256 + threadIdx.x;
    float4 v = ((const float4*)s)[i];
    bf16 h0,l0,h1,l1,h2,l2,h3,l3;
    split1(v.x,h0,l0); split1(v.y,h1,l1); split1(v.z,h2,l2); split1(v.w,h3,l3);
    ((bf162*)Hi)[2*i  ] = __halves2bfloat162(h0,h1);
    ((bf162*)Hi)[2*i+1] = __halves2bfloat162(h2,h3);
    ((bf162*)Lo)[2*i  ] = __halves2bfloat162(l0,l1);
    ((bf162*)Lo)[2*i+1] = __halves2bfloat162(l2,l3);
}

// ---- warp-MMA GEMM (projections): 128x128 tile, BK=64, 3-pass split ----
// EPI: 0=Q(scaled) 1=K 2=V^T 5=out-proj
#define BK 64
#define AS 72
#define TILE_B (128*AS*2)
#define SMEM_DYN (4*TILE_B)

template<int EPI>
__global__ __launch_bounds__(256) void tc_gemm(float* __restrict__ outf)
{
    extern __shared__ bf16 smem[];
    uint32_t sb = su32(smem);
    const int tid = threadIdx.x, wid = tid>>5, lane = tid&31;
    const int wm = wid&1, wn = wid>>1;
    const int n0 = blockIdx.x*128, m0 = blockIdx.y*128;

    const bf16 *Ahi,*Alo,*Bhi,*Blo; int K;
    if (EPI<=2){ Ahi=g_xhi; Alo=g_xlo; Bhi=g_whi[EPI]; Blo=g_wlo[EPI]; K=CC; }
    else { Ahi=g_yhi; Alo=g_ylo; Bhi=g_whi[3]; Blo=g_wlo[3]; K=CC; }
    const int Kp = K/BK, NC = 3*Kp;

    auto load_chunk = [&](int c, int b){
        int pass = c/Kp, kk = (c - pass*Kp)*BK;
        const bf16* Ap = pass<2 ? Ahi : Alo;
        const bf16* Bp = pass==1 ? Blo : Bhi;
        uint32_t sa = sb + b*TILE_B;
        uint32_t sB = sb + 2*TILE_B + b*TILE_B;
#pragma unroll
        for (int j=0;j<4;j++){
            int lin = j*256+tid, row = lin>>3, c16 = lin&7;
            CP_ASYNC16(sa + row*(AS*2) + c16*16, Ap + (size_t)(m0+row)*K + kk + c16*8);
        }
#pragma unroll
        for (int j=0;j<4;j++){
            int lin = j*256+tid, row = lin>>3, c16 = lin&7;
            CP_ASYNC16(sB + row*(AS*2) + c16*16, Bp + (size_t)(n0+row)*K + kk + c16*8);
        }
        CP_COMMIT();
    };

    float acc[4][4][4];
#pragma unroll
    for (int mi=0;mi<4;mi++)
#pragma unroll
        for (int ni=0;ni<4;ni++)
#pragma unroll
            for (int r=0;r<4;r++) acc[mi][ni][r] = 0.0f;

    load_chunk(0,0);
    for (int c=0;c<NC;c++){
        if (c+1<NC){ load_chunk(c+1,(c+1)&1); asm volatile("cp.async.wait_group 1;":::"memory"); }
        else asm volatile("cp.async.wait_group 0;":::"memory");
        __syncthreads();
        uint32_t sa = sb + (c&1)*TILE_B;
        uint32_t sB = sb + 2*TILE_B + (c&1)*TILE_B;
#pragma unroll
        for (int ks=0;ks<BK;ks+=16){
            uint32_t af[4][4], bfr[4][2];
#pragma unroll
            for (int mi=0;mi<4;mi++){
                int r = wm*64 + mi*16 + (lane&15);
                uint32_t addr = sa + r*(AS*2) + (ks + ((lane>>4)<<3))*2;
                LDSM4(af[mi][0],af[mi][1],af[mi][2],af[mi][3], addr);
            }
#pragma unroll
            for (int g=0;g<2;g++){
                int nr = wn*32 + g*16 + ((lane>>4)<<3) + (lane&7);
                uint32_t addr = sB + nr*(AS*2) + (ks + ((lane>>3)&1)*8)*2;
                uint32_t r0,r1,r2,r3;
                LDSM4(r0,r1,r2,r3, addr);
                bfr[2*g][0]=r0; bfr[2*g][1]=r1; bfr[2*g+1][0]=r2; bfr[2*g+1][1]=r3;
            }
#pragma unroll
            for (int mi=0;mi<4;mi++)
#pragma unroll
                for (int ni=0;ni<4;ni++)
                    mma16816(acc[mi][ni], af[mi], bfr[ni]);
        }
        __syncthreads();
    }

    const int lrow = lane>>2, lcol = (lane&3)*2;
#pragma unroll
    for (int mi=0;mi<4;mi++){
#pragma unroll
        for (int ni=0;ni<4;ni++){
            int cw = wn*32 + ni*8 + lcol;
            int n  = n0 + cw;
#pragma unroll
            for (int half=0; half<2; half++){
                int m = m0 + wm*64 + mi*16 + lrow + half*8;
                float v0 = acc[mi][ni][2*half], v1 = acc[mi][ni][2*half+1];
                if (EPI==0 || EPI==1){
                    if (EPI==0){ v0 *= 0.08838834764831845f; v1 *= 0.08838834764831845f; }
                    int b = m>>11, t = m&(TT-1), h = blockIdx.x, d = cw;
                    bf16* Hi = (EPI==0)?g_qhi:g_khi;  bf16* Lo = (EPI==0)?g_qlo:g_klo;
                    bf16 h0,l0,h1,l1; split1(v0,h0,l0); split1(v1,h1,l1);
                    size_t o = ((size_t)(b*NH+h)*TT + t)*HD + d;
                    *(bf162*)&Hi[o] = __halves2bfloat162(h0,h1);
                    *(bf162*)&Lo[o] = __halves2bfloat162(l0,l1);
                } else if (EPI==2){
                    int b = m>>11, t = m&(TT-1), h = blockIdx.x, d = cw;
                    bf16 h0,l0,h1,l1; split1(v0,h0,l0); split1(v1,h1,l1);
                    size_t o = ((size_t)(b*NH+h)*HD + d)*TT + t;
                    g_vthi[o] = h0; g_vtlo[o] = l0;
                    g_vthi[o+TT] = h1; g_vtlo[o+TT] = l1;
                } else {
                    *(float2*)&outf[(size_t)m*CC + n] = make_float2(v0, v1);
                }
            }
        }
    }
}

// ---- fused flash attention: S=QK^T (3-pass), online softmax, acc+=PV (3-pass)
// Grid (16, 32); 8 warps; warp w owns Q rows [16w,16w+16). K/V tiles of 128 keys.
#define SK 136                 // smem stride in halves (272B, ldmatrix conflict-free)
#define FTB (128*SK*2)         // 34816 B per tile
#define FS_SMEM (6*FTB)        // Qh,Ql,Kh,Kl,Vh,Vl = 208896 B

__global__ __launch_bounds__(256) void flash_k()
{
    extern __shared__ bf16 fsm[];
    uint32_t sb = su32(fsm);
    const uint32_t QH=sb, QL=sb+FTB, KH=sb+2*FTB, KL=sb+3*FTB, VH=sb+4*FTB, VL=sb+5*FTB;
    const int tid = threadIdx.x, wid = tid>>5, lane = tid&31;
    const int bh = blockIdx.y, q0 = blockIdx.x*128;

    const bf16* Qh = g_qhi + ((size_t)bh*TT + q0)*HD;
    const bf16* Ql = g_qlo + ((size_t)bh*TT + q0)*HD;
    const bf16* Kh = g_khi + (size_t)bh*TT*HD;
    const bf16* Kl = g_klo + (size_t)bh*TT*HD;
    const bf16* Vh = g_vthi + (size_t)bh*HD*TT;
    const bf16* Vl = g_vtlo + (size_t)bh*HD*TT;

    auto ldtile = [&](uint32_t dst, const bf16* src, int stride, int coloff){
#pragma unroll
        for (int j=0;j<8;j++){
            int lin = j*256+tid, row = lin>>4, c = lin&15;
            CP_ASYNC16(dst + row*(SK*2) + c*16, src + (size_t)row*stride + coloff + c*8);
        }
    };

    // Q tiles once
    ldtile(QH, Qh, HD, 0);
    ldtile(QL, Ql, HD, 0);
    CP_COMMIT();

    float acc[16][4];
#pragma unroll
    for (int j=0;j<16;j++){ acc[j][0]=0;acc[j][1]=0;acc[j][2]=0;acc[j][3]=0; }
    float m0=-1e30f, m1=-1e30f, l0=0.0f, l1=0.0f;

    for (int kt=0; kt<TT/128; kt++){
        __syncthreads();                      // prior tile reads done
        ldtile(KH, Kh + (size_t)kt*128*HD, HD, 0);
        ldtile(KL, Kl + (size_t)kt*128*HD, HD, 0);
        ldtile(VH, Vh, TT, kt*128);
        ldtile(VL, Vl, TT, kt*128);
        CP_COMMIT();
        asm volatile("cp.async.wait_group 0;":::"memory");
        __syncthreads();

        // ---- S = Q K^T (3-pass) ----
        float S[16][4];
#pragma unroll
        for (int j=0;j<16;j++){ S[j][0]=0;S[j][1]=0;S[j][2]=0;S[j][3]=0; }
#pragma unroll
        for (int pass=0; pass<3; pass++){
            uint32_t qb = (pass<2)?QH:QL;
            uint32_t kb = (pass==1)?KL:KH;
#pragma unroll
            for (int ks=0;ks<8;ks++){
                uint32_t a[4];
                int ar = wid*16 + (lane&15);
                LDSM4(a[0],a[1],a[2],a[3], qb + ar*(SK*2) + (ks*16 + ((lane>>4)<<3))*2);
#pragma unroll
                for (int g=0;g<8;g++){
                    int nr = g*16 + ((lane>>4)<<3) + (lane&7);
                    uint32_t r0,r1,r2,r3;
                    LDSM4(r0,r1,r2,r3, kb + nr*(SK*2) + (ks*16 + ((lane>>3)&1)*8)*2);
                    uint32_t b0[2]={r0,r1}, b1[2]={r2,r3};
                    mma16816(S[2*g],   a, b0);
                    mma16816(S[2*g+1], a, b1);
                }
            }
        }

        // ---- online softmax ----
        float mx0=-1e30f, mx1=-1e30f;
#pragma unroll
        for (int j=0;j<16;j++){
            mx0 = fmaxf(mx0, fmaxf(S[j][0],S[j][1]));
            mx1 = fmaxf(mx1, fmaxf(S[j][2],S[j][3]));
        }
        mx0 = fmaxf(mx0, __shfl_xor_sync(~0u,mx0,1)); mx0 = fmaxf(mx0, __shfl_xor_sync(~0u,mx0,2));
        mx1 = fmaxf(mx1, __shfl_xor_sync(~0u,mx1,1)); mx1 = fmaxf(mx1, __shfl_xor_sync(~0u,mx1,2));
        float mn0 = fmaxf(m0,mx0), mn1 = fmaxf(m1,mx1);
        float c0 = __expf(m0-mn0), c1 = __expf(m1-mn1);
        float ls0=0.0f, ls1=0.0f;
#pragma unroll
        for (int j=0;j<16;j++){
            S[j][0]=__expf(S[j][0]-mn0); S[j][1]=__expf(S[j][1]-mn0); ls0 += S[j][0]+S[j][1];
            S[j][2]=__expf(S[j][2]-mn1); S[j][3]=__expf(S[j][3]-mn1); ls1 += S[j][2]+S[j][3];
        }
        ls0 += __shfl_xor_sync(~0u,ls0,1); ls0 += __shfl_xor_sync(~0u,ls0,2);
        ls1 += __shfl_xor_sync(~0u,ls1,1); ls1 += __shfl_xor_sync(~0u,ls1,2);
        l0 = l0*c0 + ls0; l1 = l1*c1 + ls1; m0 = mn0; m1 = mn1;
#pragma unroll
        for (int j=0;j<16;j++){ acc[j][0]*=c0; acc[j][1]*=c0; acc[j][2]*=c1; acc[j][3]*=c1; }

        // ---- P hi frags (C-frag -> A-frag identity) ----
        uint32_t ph[8][4];
#pragma unroll
        for (int ks=0;ks<8;ks++){
            ph[ks][0] = pack_hi(S[2*ks][0],   S[2*ks][1]);
            ph[ks][1] = pack_hi(S[2*ks][2],   S[2*ks][3]);
            ph[ks][2] = pack_hi(S[2*ks+1][0], S[2*ks+1][1]);
            ph[ks][3] = pack_hi(S[2*ks+1][2], S[2*ks+1][3]);
        }
        // acc += Phi*Vhi + Phi*Vlo
#pragma unroll
        for (int ks=0;ks<8;ks++){
#pragma unroll
            for (int vb=0; vb<2; vb++){
                uint32_t base = vb ? VL : VH;
#pragma unroll
                for (int g=0;g<8;g++){
                    int nr = g*16 + ((lane>>4)<<3) + (lane&7);
                    uint32_t r0,r1,r2,r3;
                    LDSM4(r0,r1,r2,r3, base + nr*(SK*2) + (ks*16 + ((lane>>3)&1)*8)*2);
                    uint32_t b0[2]={r0,r1}, b1[2]={r2,r3};
                    mma16816(acc[2*g],   ph[ks], b0);
                    mma16816(acc[2*g+1], ph[ks], b1);
                }
            }
        }
        // P lo frags, acc += Plo*Vhi
#pragma unroll
        for (int ks=0;ks<8;ks++){
            ph[ks][0] = pack_lo(S[2*ks][0],   S[2*ks][1]);
            ph[ks][1] = pack_lo(S[2*ks][2],   S[2*ks][3]);
            ph[ks][2] = pack_lo(S[2*ks+1][0], S[2*ks+1][1]);
            ph[ks][3] = pack_lo(S[2*ks+1][2], S[2*ks+1][3]);
        }
#pragma unroll
        for (int ks=0;ks<8;ks++){
#pragma unroll
            for (int g=0;g<8;g++){
                int nr = g*16 + ((lane>>4)<<3) + (lane&7);
                uint32_t r0,r1,r2,r3;
                LDSM4(r0,r1,r2,r3, VH + nr*(SK*2) + (ks*16 + ((lane>>3)&1)*8)*2);
                uint32_t b0[2]={r0,r1}, b1[2]={r2,r3};
                mma16816(acc[2*g],   ph[ks], b0);
                mma16816(acc[2*g+1], ph[ks], b1);
            }
        }
    }

    // ---- write y (split) in [B,T,C] ----
    float i0 = 1.0f/l0, i1 = 1.0f/l1;
    int b = bh>>4, h = bh&15;
    int t0 = q0 + wid*16 + (lane>>2);
#pragma unroll
    for (int j=0;j<16;j++){
        int d = j*8 + (lane&3)*2;
        {
            float v0 = acc[j][0]*i0, v1 = acc[j][1]*i0;
            bf16 h0,L0,h1,L1; split1(v0,h0,L0); split1(v1,h1,L1);
            size_t o = ((size_t)(b*TT + t0))*CC + h*HD + d;
            *(bf162*)&g_yhi[o] = __halves2bfloat162(h0,h1);
            *(bf162*)&g_ylo[o] = __halves2bfloat162(L0,L1);
        }
        {
            float v0 = acc[j][2]*i1, v1 = acc[j][3]*i1;
            bf16 h0,L0,h1,L1; split1(v0,h0,L0); split1(v1,h1,L1);
            size_t o = ((size_t)(b*TT + t0 + 8))*CC + h*HD + d;
            *(bf162*)&g_yhi[o] = __halves2bfloat162(h0,h1);
            *(bf162*)&g_ylo[o] = __halves2bfloat162(L0,L1);
        }
    }
}

// ---- launch ----
extern "C" void kernel_launch(void* const* d_in, const int* in_sizes, int n_in,
                              void* d_out, int out_size)
{
    const float* x  = (const float*)d_in[0];
    const float* wq = (const float*)d_in[1];
    const float* wk = (const float*)d_in[2];
    const float* wv = (const float*)d_in[3];
    const float* wo = (const float*)d_in[4];
    float* out = (float*)d_out;

    cudaFuncSetAttribute(tc_gemm<0>, cudaFuncAttributeMaxDynamicSharedMemorySize, SMEM_DYN);
    cudaFuncSetAttribute(tc_gemm<1>, cudaFuncAttributeMaxDynamicSharedMemorySize, SMEM_DYN);
    cudaFuncSetAttribute(tc_gemm<2>, cudaFuncAttributeMaxDynamicSharedMemorySize, SMEM_DYN);
    cudaFuncSetAttribute(tc_gemm<5>, cudaFuncAttributeMaxDynamicSharedMemorySize, SMEM_DYN);
    cudaFuncSetAttribute(flash_k,   cudaFuncAttributeMaxDynamicSharedMemorySize, FS_SMEM);

    split_k<0><<<MTOT*CC/1024, 256>>>(x);
    split_k<1><<<CC*CC/1024, 256>>>(wq);
    split_k<2><<<CC*CC/1024, 256>>>(wk);
    split_k<3><<<CC*CC/1024, 256>>>(wv);
    split_k<4><<<CC*CC/1024, 256>>>(wo);

    tc_gemm<0><<<dim3(16,32), 256, SMEM_DYN>>>(nullptr);   // Q (pre-scaled)
    tc_gemm<1><<<dim3(16,32), 256, SMEM_DYN>>>(nullptr);   // K
    tc_gemm<2><<<dim3(16,32), 256, SMEM_DYN>>>(nullptr);   // V^T
    flash_k<<<dim3(TT/128, BHH), 256, FS_SMEM>>>();        // attention -> y split
    tc_gemm<5><<<dim3(16,32), 256, SMEM_DYN>>>(out);       // out-proj
}

// round 8
// speedup vs baseline: 1.1657x; 1.1657x over previous
#include <cuda_runtime.h>
#include <cuda_bf16.h>
#include <cstdint>

#define BD 2
#define TT 2048
#define CC 2048
#define NH 16
#define HD 128
#define MTOT (BD*TT)
#define BHH (BD*NH)
typedef __nv_bfloat16 bf16;
typedef __nv_bfloat162 bf162;

__device__ bf16 g_xhi[MTOT*CC], g_xlo[MTOT*CC];
__device__ bf16 g_whi[4][CC*CC], g_wlo[4][CC*CC];
__device__ bf16 g_qhi[BHH*TT*HD], g_qlo[BHH*TT*HD];
__device__ bf16 g_khi[BHH*TT*HD], g_klo[BHH*TT*HD];
__device__ bf16 g_vthi[BHH*HD*TT], g_vtlo[BHH*HD*TT];
__device__ bf16 g_yhi[MTOT*CC], g_ylo[MTOT*CC];

// ---- helpers ----
__device__ __forceinline__ uint32_t su32(const void* p){
    uint32_t a; asm("{.reg .u64 t; cvta.to.shared.u64 t,%1; cvt.u32.u64 %0,t;}":"=r"(a):"l"(p)); return a;
}
#define CP_ASYNC16(s,g) asm volatile("cp.async.cg.shared.global [%0], [%1], 16;" ::"r"(s),"l"(g))
#define CP_COMMIT() asm volatile("cp.async.commit_group;" ::: "memory")
#define LDSM4(r0,r1,r2,r3,addr) \
    asm volatile("ldmatrix.sync.aligned.m8n8.x4.shared.b16 {%0,%1,%2,%3},[%4];" \
                 :"=r"(r0),"=r"(r1),"=r"(r2),"=r"(r3):"r"(addr))

__device__ __forceinline__ void mma16816(float* d, const uint32_t* a, const uint32_t* b){
    asm volatile("mma.sync.aligned.m16n8k16.row.col.f32.bf16.bf16.f32 "
        "{%0,%1,%2,%3},{%4,%5,%6,%7},{%8,%9},{%0,%1,%2,%3};"
        : "+f"(d[0]),"+f"(d[1]),"+f"(d[2]),"+f"(d[3])
        : "r"(a[0]),"r"(a[1]),"r"(a[2]),"r"(a[3]),"r"(b[0]),"r"(b[1]));
}

__device__ __forceinline__ void split1(float v, bf16& h, bf16& l){
    h = __float2bfloat16(v); l = __float2bfloat16(v - __bfloat162float(h));
}
__device__ __forceinline__ uint32_t pack_hi(float x, float y){
    bf162 t = __halves2bfloat162(__float2bfloat16(x), __float2bfloat16(y));
    return *(uint32_t*)&t;
}
__device__ __forceinline__ uint32_t pack_lo(float x, float y){
    bf16 hx,lx,hy,ly; split1(x,hx,lx); split1(y,hy,ly);
    bf162 t = __halves2bfloat162(lx,ly);
    return *(uint32_t*)&t;
}

// ---- split fp32 -> bf16 hi/lo ----
__global__ __launch_bounds__(256) void split_x(const float* __restrict__ s){
    int i = blockIdx.x*256 + threadIdx.x;
    float4 v = ((const float4*)s)[i];
    bf16 h0,l0,h1,l1,h2,l2,h3,l3;
    split1(v.x,h0,l0); split1(v.y,h1,l1); split1(v.z,h2,l2); split1(v.w,h3,l3);
    ((bf162*)g_xhi)[2*i  ] = __halves2bfloat162(h0,h1);
    ((bf162*)g_xhi)[2*i+1] = __halves2bfloat162(h2,h3);
    ((bf162*)g_xlo)[2*i  ] = __halves2bfloat162(l0,l1);
    ((bf162*)g_xlo)[2*i+1] = __halves2bfloat162(l2,l3);
}
__global__ __launch_bounds__(256) void split_w(const float* __restrict__ w0,
                                               const float* __restrict__ w1,
                                               const float* __restrict__ w2,
                                               const float* __restrict__ w3){
    int wi = blockIdx.y;
    const float* s = (wi==0)?w0:(wi==1)?w1:(wi==2)?w2:w3;
    int i = blockIdx.x*256 + threadIdx.x;
    float4 v = ((const float4*)s)[i];
    bf16 h0,l0,h1,l1,h2,l2,h3,l3;
    split1(v.x,h0,l0); split1(v.y,h1,l1); split1(v.z,h2,l2); split1(v.w,h3,l3);
    ((bf162*)g_whi[wi])[2*i  ] = __halves2bfloat162(h0,h1);
    ((bf162*)g_whi[wi])[2*i+1] = __halves2bfloat162(h2,h3);
    ((bf162*)g_wlo[wi])[2*i  ] = __halves2bfloat162(l0,l1);
    ((bf162*)g_wlo[wi])[2*i+1] = __halves2bfloat162(l2,l3);
}

// ---- warp-MMA GEMM: 128x128 tile, BK=64, 3-pass split ----
// MODE 0: QKV (blockIdx.z: 0=Q scaled, 1=K, 2=V^T).  MODE 1: out-proj.
#define BK 64
#define AS 72
#define TILE_B (128*AS*2)
#define SMEM_DYN (4*TILE_B)

template<int MODE>
__global__ __launch_bounds__(256, 2) void tc_gemm(float* __restrict__ outf)
{
    extern __shared__ bf16 smem[];
    uint32_t sb = su32(smem);
    const int tid = threadIdx.x, wid = tid>>5, lane = tid&31;
    const int wm = wid&1, wn = wid>>1;
    const int n0 = blockIdx.x*128, m0 = blockIdx.y*128, z = blockIdx.z;

    const bf16 *Ahi,*Alo,*Bhi,*Blo;
    if (MODE==0){ Ahi=g_xhi; Alo=g_xlo; Bhi=g_whi[z]; Blo=g_wlo[z]; }
    else        { Ahi=g_yhi; Alo=g_ylo; Bhi=g_whi[3]; Blo=g_wlo[3]; }
    const int K = CC, Kp = K/BK, NC = 3*Kp;

    auto load_chunk = [&](int c, int b){
        int pass = c/Kp, kk = (c - pass*Kp)*BK;
        const bf16* Ap = pass<2 ? Ahi : Alo;
        const bf16* Bp = pass==1 ? Blo : Bhi;
        uint32_t sa = sb + b*TILE_B;
        uint32_t sB = sb + 2*TILE_B + b*TILE_B;
#pragma unroll
        for (int j=0;j<4;j++){
            int lin = j*256+tid, row = lin>>3, c16 = lin&7;
            CP_ASYNC16(sa + row*(AS*2) + c16*16, Ap + (size_t)(m0+row)*K + kk + c16*8);
        }
#pragma unroll
        for (int j=0;j<4;j++){
            int lin = j*256+tid, row = lin>>3, c16 = lin&7;
            CP_ASYNC16(sB + row*(AS*2) + c16*16, Bp + (size_t)(n0+row)*K + kk + c16*8);
        }
        CP_COMMIT();
    };

    float acc[4][4][4];
#pragma unroll
    for (int mi=0;mi<4;mi++)
#pragma unroll
        for (int ni=0;ni<4;ni++)
#pragma unroll
            for (int r=0;r<4;r++) acc[mi][ni][r] = 0.0f;

    load_chunk(0,0);
    for (int c=0;c<NC;c++){
        if (c+1<NC){ load_chunk(c+1,(c+1)&1); asm volatile("cp.async.wait_group 1;":::"memory"); }
        else asm volatile("cp.async.wait_group 0;":::"memory");
        __syncthreads();
        uint32_t sa = sb + (c&1)*TILE_B;
        uint32_t sB = sb + 2*TILE_B + (c&1)*TILE_B;
#pragma unroll
        for (int ks=0;ks<BK;ks+=16){
            uint32_t af[4][4], bfr[4][2];
#pragma unroll
            for (int mi=0;mi<4;mi++){
                int r = wm*64 + mi*16 + (lane&15);
                uint32_t addr = sa + r*(AS*2) + (ks + ((lane>>4)<<3))*2;
                LDSM4(af[mi][0],af[mi][1],af[mi][2],af[mi][3], addr);
            }
#pragma unroll
            for (int g=0;g<2;g++){
                int nr = wn*32 + g*16 + ((lane>>4)<<3) + (lane&7);
                uint32_t addr = sB + nr*(AS*2) + (ks + ((lane>>3)&1)*8)*2;
                uint32_t r0,r1,r2,r3;
                LDSM4(r0,r1,r2,r3, addr);
                bfr[2*g][0]=r0; bfr[2*g][1]=r1; bfr[2*g+1][0]=r2; bfr[2*g+1][1]=r3;
            }
#pragma unroll
            for (int mi=0;mi<4;mi++)
#pragma unroll
                for (int ni=0;ni<4;ni++)
                    mma16816(acc[mi][ni], af[mi], bfr[ni]);
        }
        __syncthreads();
    }

    const int lrow = lane>>2, lcol = (lane&3)*2;
#pragma unroll
    for (int mi=0;mi<4;mi++){
#pragma unroll
        for (int ni=0;ni<4;ni++){
            int cw = wn*32 + ni*8 + lcol;
            int n  = n0 + cw;
#pragma unroll
            for (int half=0; half<2; half++){
                int m = m0 + wm*64 + mi*16 + lrow + half*8;
                float v0 = acc[mi][ni][2*half], v1 = acc[mi][ni][2*half+1];
                if (MODE==0){
                    int b = m>>11, t = m&(TT-1), h = blockIdx.x, d = cw;
                    if (z==0){
                        v0 *= 0.08838834764831845f; v1 *= 0.08838834764831845f;
                        bf16 h0,l0,h1,l1; split1(v0,h0,l0); split1(v1,h1,l1);
                        size_t o = ((size_t)(b*NH+h)*TT + t)*HD + d;
                        *(bf162*)&g_qhi[o] = __halves2bfloat162(h0,h1);
                        *(bf162*)&g_qlo[o] = __halves2bfloat162(l0,l1);
                    } else if (z==1){
                        bf16 h0,l0,h1,l1; split1(v0,h0,l0); split1(v1,h1,l1);
                        size_t o = ((size_t)(b*NH+h)*TT + t)*HD + d;
                        *(bf162*)&g_khi[o] = __halves2bfloat162(h0,h1);
                        *(bf162*)&g_klo[o] = __halves2bfloat162(l0,l1);
                    } else {
                        bf16 h0,l0,h1,l1; split1(v0,h0,l0); split1(v1,h1,l1);
                        size_t o = ((size_t)(b*NH+h)*HD + d)*TT + t;
                        g_vthi[o] = h0; g_vtlo[o] = l0;
                        g_vthi[o+TT] = h1; g_vtlo[o+TT] = l1;
                    }
                } else {
                    *(float2*)&outf[(size_t)m*CC + n] = make_float2(v0, v1);
                }
            }
        }
    }
}

// ---- fused flash attention, merged 3-pass sweeps ----
#define SK 136
#define FTB (128*SK*2)
#define FS_SMEM (6*FTB)

__global__ __launch_bounds__(256) void flash_k()
{
    extern __shared__ bf16 fsm[];
    uint32_t sb = su32(fsm);
    const uint32_t QH=sb, QL=sb+FTB, KH=sb+2*FTB, KL=sb+3*FTB, VH=sb+4*FTB, VL=sb+5*FTB;
    const int tid = threadIdx.x, wid = tid>>5, lane = tid&31;
    const int bh = blockIdx.y, q0 = blockIdx.x*128;

    const bf16* Qh = g_qhi + ((size_t)bh*TT + q0)*HD;
    const bf16* Ql = g_qlo + ((size_t)bh*TT + q0)*HD;
    const bf16* Kh = g_khi + (size_t)bh*TT*HD;
    const bf16* Kl = g_klo + (size_t)bh*TT*HD;
    const bf16* Vh = g_vthi + (size_t)bh*HD*TT;
    const bf16* Vl = g_vtlo + (size_t)bh*HD*TT;

    auto ldtile = [&](uint32_t dst, const bf16* src, int stride, int coloff){
#pragma unroll
        for (int j=0;j<8;j++){
            int lin = j*256+tid, row = lin>>4, c = lin&15;
            CP_ASYNC16(dst + row*(SK*2) + c*16, src + (size_t)row*stride + coloff + c*8);
        }
    };

    ldtile(QH, Qh, HD, 0);
    ldtile(QL, Ql, HD, 0);
    CP_COMMIT();

    float acc[16][4];
#pragma unroll
    for (int j=0;j<16;j++){ acc[j][0]=0;acc[j][1]=0;acc[j][2]=0;acc[j][3]=0; }
    float m0=-1e30f, m1=-1e30f, l0=0.0f, l1=0.0f;

    for (int kt=0; kt<TT/128; kt++){
        __syncthreads();
        ldtile(KH, Kh + (size_t)kt*128*HD, HD, 0);
        ldtile(KL, Kl + (size_t)kt*128*HD, HD, 0);
        ldtile(VH, Vh, TT, kt*128);
        ldtile(VL, Vl, TT, kt*128);
        CP_COMMIT();
        asm volatile("cp.async.wait_group 0;":::"memory");
        __syncthreads();

        // ---- S = QK^T, merged 3-pass sweep ----
        float S[16][4];
#pragma unroll
        for (int j=0;j<16;j++){ S[j][0]=0;S[j][1]=0;S[j][2]=0;S[j][3]=0; }
#pragma unroll
        for (int ks=0;ks<8;ks++){
            uint32_t qh[4], ql[4];
            int ar = wid*16 + (lane&15);
            uint32_t acol = (ks*16 + ((lane>>4)<<3))*2;
            LDSM4(qh[0],qh[1],qh[2],qh[3], QH + ar*(SK*2) + acol);
            LDSM4(ql[0],ql[1],ql[2],ql[3], QL + ar*(SK*2) + acol);
#pragma unroll
            for (int g=0;g<8;g++){
                int nr = g*16 + ((lane>>4)<<3) + (lane&7);
                uint32_t bcol = (ks*16 + ((lane>>3)&1)*8)*2;
                uint32_t h0,h1,h2,h3, e0,e1,e2,e3;
                LDSM4(h0,h1,h2,h3, KH + nr*(SK*2) + bcol);
                LDSM4(e0,e1,e2,e3, KL + nr*(SK*2) + bcol);
                uint32_t bh0[2]={h0,h1}, bh1[2]={h2,h3}, bl0[2]={e0,e1}, bl1[2]={e2,e3};
                mma16816(S[2*g],   qh, bh0); mma16816(S[2*g+1], qh, bh1);
                mma16816(S[2*g],   qh, bl0); mma16816(S[2*g+1], qh, bl1);
                mma16816(S[2*g],   ql, bh0); mma16816(S[2*g+1], ql, bh1);
            }
        }

        // ---- online softmax ----
        float mx0=-1e30f, mx1=-1e30f;
#pragma unroll
        for (int j=0;j<16;j++){
            mx0 = fmaxf(mx0, fmaxf(S[j][0],S[j][1]));
            mx1 = fmaxf(mx1, fmaxf(S[j][2],S[j][3]));
        }
        mx0 = fmaxf(mx0, __shfl_xor_sync(~0u,mx0,1)); mx0 = fmaxf(mx0, __shfl_xor_sync(~0u,mx0,2));
        mx1 = fmaxf(mx1, __shfl_xor_sync(~0u,mx1,1)); mx1 = fmaxf(mx1, __shfl_xor_sync(~0u,mx1,2));
        float mn0 = fmaxf(m0,mx0), mn1 = fmaxf(m1,mx1);
        float c0 = __expf(m0-mn0), c1 = __expf(m1-mn1);
        float ls0=0.0f, ls1=0.0f;
#pragma unroll
        for (int j=0;j<16;j++){
            S[j][0]=__expf(S[j][0]-mn0); S[j][1]=__expf(S[j][1]-mn0); ls0 += S[j][0]+S[j][1];
            S[j][2]=__expf(S[j][2]-mn1); S[j][3]=__expf(S[j][3]-mn1); ls1 += S[j][2]+S[j][3];
        }
        ls0 += __shfl_xor_sync(~0u,ls0,1); ls0 += __shfl_xor_sync(~0u,ls0,2);
        ls1 += __shfl_xor_sync(~0u,ls1,1); ls1 += __shfl_xor_sync(~0u,ls1,2);
        l0 = l0*c0 + ls0; l1 = l1*c1 + ls1; m0 = mn0; m1 = mn1;
#pragma unroll
        for (int j=0;j<16;j++){ acc[j][0]*=c0; acc[j][1]*=c0; acc[j][2]*=c1; acc[j][3]*=c1; }

        // ---- acc += P V, merged 3-pass sweep, per-ks P packing ----
#pragma unroll
        for (int ks=0;ks<8;ks++){
            uint32_t ph[4], pl[4];
            ph[0]=pack_hi(S[2*ks][0],  S[2*ks][1]);   ph[1]=pack_hi(S[2*ks][2],  S[2*ks][3]);
            ph[2]=pack_hi(S[2*ks+1][0],S[2*ks+1][1]); ph[3]=pack_hi(S[2*ks+1][2],S[2*ks+1][3]);
            pl[0]=pack_lo(S[2*ks][0],  S[2*ks][1]);   pl[1]=pack_lo(S[2*ks][2],  S[2*ks][3]);
            pl[2]=pack_lo(S[2*ks+1][0],S[2*ks+1][1]); pl[3]=pack_lo(S[2*ks+1][2],S[2*ks+1][3]);
#pragma unroll
            for (int g=0;g<8;g++){
                int nr = g*16 + ((lane>>4)<<3) + (lane&7);
                uint32_t bcol = (ks*16 + ((lane>>3)&1)*8)*2;
                uint32_t h0,h1,h2,h3, e0,e1,e2,e3;
                LDSM4(h0,h1,h2,h3, VH + nr*(SK*2) + bcol);
                LDSM4(e0,e1,e2,e3, VL + nr*(SK*2) + bcol);
                uint32_t bh0[2]={h0,h1}, bh1[2]={h2,h3}, bl0[2]={e0,e1}, bl1[2]={e2,e3};
                mma16816(acc[2*g],   ph, bh0); mma16816(acc[2*g+1], ph, bh1);
                mma16816(acc[2*g],   ph, bl0); mma16816(acc[2*g+1], ph, bl1);
                mma16816(acc[2*g],   pl, bh0); mma16816(acc[2*g+1], pl, bh1);
            }
        }
    }

    // ---- write y (split) in [B,T,C] ----
    float i0 = 1.0f/l0, i1 = 1.0f/l1;
    int b = bh>>4, h = bh&15;
    int t0 = q0 + wid*16 + (lane>>2);
#pragma unroll
    for (int j=0;j<16;j++){
        int d = j*8 + (lane&3)*2;
        {
            float v0 = acc[j][0]*i0, v1 = acc[j][1]*i0;
            bf16 h0,L0,h1,L1; split1(v0,h0,L0); split1(v1,h1,L1);
            size_t o = ((size_t)(b*TT + t0))*CC + h*HD + d;
            *(bf162*)&g_yhi[o] = __halves2bfloat162(h0,h1);
            *(bf162*)&g_ylo[o] = __halves2bfloat162(L0,L1);
        }
        {
            float v0 = acc[j][2]*i1, v1 = acc[j][3]*i1;
            bf16 h0,L0,h1,L1; split1(v0,h0,L0); split1(v1,h1,L1);
            size_t o = ((size_t)(b*TT + t0 + 8))*CC + h*HD + d;
            *(bf162*)&g_yhi[o] = __halves2bfloat162(h0,h1);
            *(bf162*)&g_ylo[o] = __halves2bfloat162(L0,L1);
        }
    }
}

// ---- launch ----
extern "C" void kernel_launch(void* const* d_in, const int* in_sizes, int n_in,
                              void* d_out, int out_size)
{
    const float* x  = (const float*)d_in[0];
    const float* wq = (const float*)d_in[1];
    const float* wk = (const float*)d_in[2];
    const float* wv = (const float*)d_in[3];
    const float* wo = (const float*)d_in[4];
    float* out = (float*)d_out;

    cudaFuncSetAttribute(tc_gemm<0>, cudaFuncAttributeMaxDynamicSharedMemorySize, SMEM_DYN);
    cudaFuncSetAttribute(tc_gemm<1>, cudaFuncAttributeMaxDynamicSharedMemorySize, SMEM_DYN);
    cudaFuncSetAttribute(flash_k,   cudaFuncAttributeMaxDynamicSharedMemorySize, FS_SMEM);

    split_x<<<MTOT*CC/1024, 256>>>(x);
    split_w<<<dim3(CC*CC/1024, 4), 256>>>(wq, wk, wv, wo);

    tc_gemm<0><<<dim3(16,32,3), 256, SMEM_DYN>>>(nullptr);  // Q,K,V^T
    flash_k<<<dim3(TT/128, BHH), 256, FS_SMEM>>>();          // attention -> y split
    tc_gemm<1><<<dim3(16,32), 256, SMEM_DYN>>>(out);         // out-proj
}

// round 9
// speedup vs baseline: 1.1693x; 1.0031x over previous
#include <cuda_runtime.h>
#include <cuda_bf16.h>
#include <cstdint>

#define BD 2
#define TT 2048
#define CC 2048
#define NH 16
#define HD 128
#define MTOT (BD*TT)
#define BHH (BD*NH)
typedef __nv_bfloat16 bf16;
typedef __nv_bfloat162 bf162;

__device__ bf16 g_xhi[MTOT*CC], g_xlo[MTOT*CC];
__device__ bf16 g_whi[4][CC*CC], g_wlo[4][CC*CC];
__device__ bf16 g_qhi[BHH*TT*HD], g_qlo[BHH*TT*HD];
__device__ bf16 g_khi[BHH*TT*HD], g_klo[BHH*TT*HD];
__device__ bf16 g_vthi[BHH*HD*TT], g_vtlo[BHH*HD*TT];
__device__ bf16 g_yhi[MTOT*CC], g_ylo[MTOT*CC];

// ---- helpers ----
__device__ __forceinline__ uint32_t su32(const void* p){
    uint32_t a; asm("{.reg .u64 t; cvta.to.shared.u64 t,%1; cvt.u32.u64 %0,t;}":"=r"(a):"l"(p)); return a;
}
#define CP_ASYNC16(s,g) asm volatile("cp.async.cg.shared.global [%0], [%1], 16;" ::"r"(s),"l"(g))
#define CP_COMMIT() asm volatile("cp.async.commit_group;" ::: "memory")
#define LDSM4(r0,r1,r2,r3,addr) \
    asm volatile("ldmatrix.sync.aligned.m8n8.x4.shared.b16 {%0,%1,%2,%3},[%4];" \
                 :"=r"(r0),"=r"(r1),"=r"(r2),"=r"(r3):"r"(addr))

__device__ __forceinline__ void mma16816(float* d, const uint32_t* a, const uint32_t* b){
    asm volatile("mma.sync.aligned.m16n8k16.row.col.f32.bf16.bf16.f32 "
        "{%0,%1,%2,%3},{%4,%5,%6,%7},{%8,%9},{%0,%1,%2,%3};"
        : "+f"(d[0]),"+f"(d[1]),"+f"(d[2]),"+f"(d[3])
        : "r"(a[0]),"r"(a[1]),"r"(a[2]),"r"(a[3]),"r"(b[0]),"r"(b[1]));
}

__device__ __forceinline__ void split1(float v, bf16& h, bf16& l){
    h = __float2bfloat16(v); l = __float2bfloat16(v - __bfloat162float(h));
}
__device__ __forceinline__ uint32_t pack_hi(float x, float y){
    bf162 t = __halves2bfloat162(__float2bfloat16(x), __float2bfloat16(y));
    return *(uint32_t*)&t;
}
__device__ __forceinline__ uint32_t pack_lo(float x, float y){
    bf16 hx,lx,hy,ly; split1(x,hx,lx); split1(y,hy,ly);
    bf162 t = __halves2bfloat162(lx,ly);
    return *(uint32_t*)&t;
}

// ---- split fp32 -> bf16 hi/lo ----
__global__ __launch_bounds__(256) void split_x(const float* __restrict__ s){
    int i = blockIdx.x*256 + threadIdx.x;
    float4 v = ((const float4*)s)[i];
    bf16 h0,l0,h1,l1,h2,l2,h3,l3;
    split1(v.x,h0,l0); split1(v.y,h1,l1); split1(v.z,h2,l2); split1(v.w,h3,l3);
    ((bf162*)g_xhi)[2*i  ] = __halves2bfloat162(h0,h1);
    ((bf162*)g_xhi)[2*i+1] = __halves2bfloat162(h2,h3);
    ((bf162*)g_xlo)[2*i  ] = __halves2bfloat162(l0,l1);
    ((bf162*)g_xlo)[2*i+1] = __halves2bfloat162(l2,l3);
}
__global__ __launch_bounds__(256) void split_w(const float* __restrict__ w0,
                                               const float* __restrict__ w1,
                                               const float* __restrict__ w2,
                                               const float* __restrict__ w3){
    int wi = blockIdx.y;
    const float* s = (wi==0)?w0:(wi==1)?w1:(wi==2)?w2:w3;
    int i = blockIdx.x*256 + threadIdx.x;
    float4 v = ((const float4*)s)[i];
    bf16 h0,l0,h1,l1,h2,l2,h3,l3;
    split1(v.x,h0,l0); split1(v.y,h1,l1); split1(v.z,h2,l2); split1(v.w,h3,l3);
    ((bf162*)g_whi[wi])[2*i  ] = __halves2bfloat162(h0,h1);
    ((bf162*)g_whi[wi])[2*i+1] = __halves2bfloat162(h2,h3);
    ((bf162*)g_wlo[wi])[2*i  ] = __halves2bfloat162(l0,l1);
    ((bf162*)g_wlo[wi])[2*i+1] = __halves2bfloat162(l2,l3);
}

// ---- warp-MMA GEMM: 128x128 tile, 4 warps (64x64 warp tile), BK=64 ----
// MODE 0: QKV (z: 0=Q scaled, 1=K, 2=V^T).  MODE 1: out-proj.
#define BK 64
#define AS 72
#define TILE_B (128*AS*2)
#define SMEM_DYN (4*TILE_B)

template<int MODE>
__global__ __launch_bounds__(128, 2) void tc_gemm(float* __restrict__ outf)
{
    extern __shared__ bf16 smem[];
    uint32_t sb = su32(smem);
    const int tid = threadIdx.x, wid = tid>>5, lane = tid&31;
    const int wm = wid&1, wn = wid>>1;       // 2x2 warps, 64x64 tiles
    const int n0 = blockIdx.x*128, m0 = blockIdx.y*128, z = blockIdx.z;

    const bf16 *Ahi,*Alo,*Bhi,*Blo;
    if (MODE==0){ Ahi=g_xhi; Alo=g_xlo; Bhi=g_whi[z]; Blo=g_wlo[z]; }
    else        { Ahi=g_yhi; Alo=g_ylo; Bhi=g_whi[3]; Blo=g_wlo[3]; }
    const int K = CC, Kp = K/BK, NC = 3*Kp;

    auto load_chunk = [&](int c, int b){
        int pass = c/Kp, kk = (c - pass*Kp)*BK;
        const bf16* Ap = pass<2 ? Ahi : Alo;
        const bf16* Bp = pass==1 ? Blo : Bhi;
        uint32_t sa = sb + b*TILE_B;
        uint32_t sB = sb + 2*TILE_B + b*TILE_B;
#pragma unroll
        for (int j=0;j<8;j++){
            int lin = j*128+tid, row = lin>>3, c16 = lin&7;
            CP_ASYNC16(sa + row*(AS*2) + c16*16, Ap + (size_t)(m0+row)*K + kk + c16*8);
        }
#pragma unroll
        for (int j=0;j<8;j++){
            int lin = j*128+tid, row = lin>>3, c16 = lin&7;
            CP_ASYNC16(sB + row*(AS*2) + c16*16, Bp + (size_t)(n0+row)*K + kk + c16*8);
        }
        CP_COMMIT();
    };

    float acc[4][8][4];
#pragma unroll
    for (int mi=0;mi<4;mi++)
#pragma unroll
        for (int ni=0;ni<8;ni++)
#pragma unroll
            for (int r=0;r<4;r++) acc[mi][ni][r] = 0.0f;

    load_chunk(0,0);
    for (int c=0;c<NC;c++){
        if (c+1<NC){ load_chunk(c+1,(c+1)&1); asm volatile("cp.async.wait_group 1;":::"memory"); }
        else asm volatile("cp.async.wait_group 0;":::"memory");
        __syncthreads();
        uint32_t sa = sb + (c&1)*TILE_B;
        uint32_t sB = sb + 2*TILE_B + (c&1)*TILE_B;
#pragma unroll
        for (int ks=0;ks<BK;ks+=16){
            uint32_t af[4][4], bfr[8][2];
#pragma unroll
            for (int mi=0;mi<4;mi++){
                int r = wm*64 + mi*16 + (lane&15);
                uint32_t addr = sa + r*(AS*2) + (ks + ((lane>>4)<<3))*2;
                LDSM4(af[mi][0],af[mi][1],af[mi][2],af[mi][3], addr);
            }
#pragma unroll
            for (int g=0;g<4;g++){
                int nr = wn*64 + g*16 + ((lane>>4)<<3) + (lane&7);
                uint32_t addr = sB + nr*(AS*2) + (ks + ((lane>>3)&1)*8)*2;
                uint32_t r0,r1,r2,r3;
                LDSM4(r0,r1,r2,r3, addr);
                bfr[2*g][0]=r0; bfr[2*g][1]=r1; bfr[2*g+1][0]=r2; bfr[2*g+1][1]=r3;
            }
#pragma unroll
            for (int mi=0;mi<4;mi++)
#pragma unroll
                for (int ni=0;ni<8;ni++)
                    mma16816(acc[mi][ni], af[mi], bfr[ni]);
        }
        __syncthreads();
    }

    const int lrow = lane>>2, lcol = (lane&3)*2;
#pragma unroll
    for (int mi=0;mi<4;mi++){
#pragma unroll
        for (int ni=0;ni<8;ni++){
            int cw = wn*64 + ni*8 + lcol;
            int n  = n0 + cw;
#pragma unroll
            for (int half=0; half<2; half++){
                int m = m0 + wm*64 + mi*16 + lrow + half*8;
                float v0 = acc[mi][ni][2*half], v1 = acc[mi][ni][2*half+1];
                if (MODE==0){
                    int b = m>>11, t = m&(TT-1), h = blockIdx.x, d = cw;
                    if (z==0){
                        v0 *= 0.08838834764831845f; v1 *= 0.08838834764831845f;
                        bf16 h0,l0,h1,l1; split1(v0,h0,l0); split1(v1,h1,l1);
                        size_t o = ((size_t)(b*NH+h)*TT + t)*HD + d;
                        *(bf162*)&g_qhi[o] = __halves2bfloat162(h0,h1);
                        *(bf162*)&g_qlo[o] = __halves2bfloat162(l0,l1);
                    } else if (z==1){
                        bf16 h0,l0,h1,l1; split1(v0,h0,l0); split1(v1,h1,l1);
                        size_t o = ((size_t)(b*NH+h)*TT + t)*HD + d;
                        *(bf162*)&g_khi[o] = __halves2bfloat162(h0,h1);
                        *(bf162*)&g_klo[o] = __halves2bfloat162(l0,l1);
                    } else {
                        bf16 h0,l0,h1,l1; split1(v0,h0,l0); split1(v1,h1,l1);
                        size_t o = ((size_t)(b*NH+h)*HD + d)*TT + t;
                        g_vthi[o] = h0; g_vtlo[o] = l0;
                        g_vthi[o+TT] = h1; g_vtlo[o+TT] = l1;
                    }
                } else {
                    *(float2*)&outf[(size_t)m*CC + n] = make_float2(v0, v1);
                }
            }
        }
    }
}

// ---- fused flash attention: 64q x 64k tiles, 4 warps, 2 CTAs/SM ----
#define SKQ 136               // Q/K row stride in halves (272 B)
#define SKV 72                // V row stride in halves (144 B)
#define FQH 0
#define FQL (64*SKQ*2)
#define FKH (2*64*SKQ*2)
#define FKL (3*64*SKQ*2)
#define FVH (4*64*SKQ*2)
#define FVL (4*64*SKQ*2 + 128*SKV*2)
#define FS_SMEM (4*64*SKQ*2 + 2*128*SKV*2)   // 106496

__global__ __launch_bounds__(128, 2) void flash_k()
{
    extern __shared__ bf16 fsm[];
    uint32_t sb = su32(fsm);
    const uint32_t QH=sb+FQH, QL=sb+FQL, KH=sb+FKH, KL=sb+FKL, VH=sb+FVH, VL=sb+FVL;
    const int tid = threadIdx.x, wid = tid>>5, lane = tid&31;
    const int bh = blockIdx.y, q0 = blockIdx.x*64;

    const bf16* Qh = g_qhi + ((size_t)bh*TT + q0)*HD;
    const bf16* Ql = g_qlo + ((size_t)bh*TT + q0)*HD;
    const bf16* Kh = g_khi + (size_t)bh*TT*HD;
    const bf16* Kl = g_klo + (size_t)bh*TT*HD;
    const bf16* Vh = g_vthi + (size_t)bh*HD*TT;
    const bf16* Vl = g_vtlo + (size_t)bh*HD*TT;

    // 64 rows x 128 halves (Q/K)
    auto ldQK = [&](uint32_t dst, const bf16* src){
#pragma unroll
        for (int j=0;j<8;j++){
            int lin = j*128+tid, row = lin>>4, c = lin&15;
            CP_ASYNC16(dst + row*(SKQ*2) + c*16, src + (size_t)row*HD + c*8);
        }
    };
    // 128 rows x 64 halves (V^T)
    auto ldV = [&](uint32_t dst, const bf16* src, int coloff){
#pragma unroll
        for (int j=0;j<8;j++){
            int lin = j*128+tid, row = lin>>3, c = lin&7;
            CP_ASYNC16(dst + row*(SKV*2) + c*16, src + (size_t)row*TT + coloff + c*8);
        }
    };

    ldQK(QH, Qh);
    ldQK(QL, Ql);
    CP_COMMIT();

    float acc[16][4];
#pragma unroll
    for (int j=0;j<16;j++){ acc[j][0]=0;acc[j][1]=0;acc[j][2]=0;acc[j][3]=0; }
    float m0=-1e30f, m1=-1e30f, l0=0.0f, l1=0.0f;

    for (int kt=0; kt<TT/64; kt++){
        __syncthreads();
        ldQK(KH, Kh + (size_t)kt*64*HD);
        ldQK(KL, Kl + (size_t)kt*64*HD);
        ldV(VH, Vh, kt*64);
        ldV(VL, Vl, kt*64);
        CP_COMMIT();
        asm volatile("cp.async.wait_group 0;":::"memory");
        __syncthreads();

        // ---- S = QK^T (16x64 per warp), merged 3-pass ----
        float S[8][4];
#pragma unroll
        for (int j=0;j<8;j++){ S[j][0]=0;S[j][1]=0;S[j][2]=0;S[j][3]=0; }
#pragma unroll
        for (int ks=0;ks<8;ks++){
            uint32_t qh[4], ql[4];
            int ar = wid*16 + (lane&15);
            uint32_t acol = (ks*16 + ((lane>>4)<<3))*2;
            LDSM4(qh[0],qh[1],qh[2],qh[3], QH + ar*(SKQ*2) + acol);
            LDSM4(ql[0],ql[1],ql[2],ql[3], QL + ar*(SKQ*2) + acol);
#pragma unroll
            for (int g=0;g<4;g++){
                int nr = g*16 + ((lane>>4)<<3) + (lane&7);
                uint32_t bcol = (ks*16 + ((lane>>3)&1)*8)*2;
                uint32_t h0,h1,h2,h3, e0,e1,e2,e3;
                LDSM4(h0,h1,h2,h3, KH + nr*(SKQ*2) + bcol);
                LDSM4(e0,e1,e2,e3, KL + nr*(SKQ*2) + bcol);
                uint32_t bh0[2]={h0,h1}, bh1[2]={h2,h3}, bl0[2]={e0,e1}, bl1[2]={e2,e3};
                mma16816(S[2*g],   qh, bh0); mma16816(S[2*g+1], qh, bh1);
                mma16816(S[2*g],   qh, bl0); mma16816(S[2*g+1], qh, bl1);
                mma16816(S[2*g],   ql, bh0); mma16816(S[2*g+1], ql, bh1);
            }
        }

        // ---- online softmax (rows split: regs 0,1 -> row r; 2,3 -> row r+8) ----
        float mx0=-1e30f, mx1=-1e30f;
#pragma unroll
        for (int j=0;j<8;j++){
            mx0 = fmaxf(mx0, fmaxf(S[j][0],S[j][1]));
            mx1 = fmaxf(mx1, fmaxf(S[j][2],S[j][3]));
        }
        mx0 = fmaxf(mx0, __shfl_xor_sync(~0u,mx0,1)); mx0 = fmaxf(mx0, __shfl_xor_sync(~0u,mx0,2));
        mx1 = fmaxf(mx1, __shfl_xor_sync(~0u,mx1,1)); mx1 = fmaxf(mx1, __shfl_xor_sync(~0u,mx1,2));
        float mn0 = fmaxf(m0,mx0), mn1 = fmaxf(m1,mx1);
        float c0 = __expf(m0-mn0), c1 = __expf(m1-mn1);
        float ls0=0.0f, ls1=0.0f;
#pragma unroll
        for (int j=0;j<8;j++){
            S[j][0]=__expf(S[j][0]-mn0); S[j][1]=__expf(S[j][1]-mn0); ls0 += S[j][0]+S[j][1];
            S[j][2]=__expf(S[j][2]-mn1); S[j][3]=__expf(S[j][3]-mn1); ls1 += S[j][2]+S[j][3];
        }
        ls0 += __shfl_xor_sync(~0u,ls0,1); ls0 += __shfl_xor_sync(~0u,ls0,2);
        ls1 += __shfl_xor_sync(~0u,ls1,1); ls1 += __shfl_xor_sync(~0u,ls1,2);
        l0 = l0*c0 + ls0; l1 = l1*c1 + ls1; m0 = mn0; m1 = mn1;
#pragma unroll
        for (int j=0;j<16;j++){ acc[j][0]*=c0; acc[j][1]*=c0; acc[j][2]*=c1; acc[j][3]*=c1; }

        // ---- acc += P V (merged 3-pass), k = 64 keys -> 4 ks steps ----
#pragma unroll
        for (int ks=0;ks<4;ks++){
            uint32_t ph[4], pl[4];
            ph[0]=pack_hi(S[2*ks][0],  S[2*ks][1]);   ph[1]=pack_hi(S[2*ks][2],  S[2*ks][3]);
            ph[2]=pack_hi(S[2*ks+1][0],S[2*ks+1][1]); ph[3]=pack_hi(S[2*ks+1][2],S[2*ks+1][3]);
            pl[0]=pack_lo(S[2*ks][0],  S[2*ks][1]);   pl[1]=pack_lo(S[2*ks][2],  S[2*ks][3]);
            pl[2]=pack_lo(S[2*ks+1][0],S[2*ks+1][1]); pl[3]=pack_lo(S[2*ks+1][2],S[2*ks+1][3]);
#pragma unroll
            for (int g=0;g<8;g++){
                int nr = g*16 + ((lane>>4)<<3) + (lane&7);
                uint32_t bcol = (ks*16 + ((lane>>3)&1)*8)*2;
                uint32_t h0,h1,h2,h3, e0,e1,e2,e3;
                LDSM4(h0,h1,h2,h3, VH + nr*(SKV*2) + bcol);
                LDSM4(e0,e1,e2,e3, VL + nr*(SKV*2) + bcol);
                uint32_t bh0[2]={h0,h1}, bh1[2]={h2,h3}, bl0[2]={e0,e1}, bl1[2]={e2,e3};
                mma16816(acc[2*g],   ph, bh0); mma16816(acc[2*g+1], ph, bh1);
                mma16816(acc[2*g],   ph, bl0); mma16816(acc[2*g+1], ph, bl1);
                mma16816(acc[2*g],   pl, bh0); mma16816(acc[2*g+1], pl, bh1);
            }
        }
    }

    // ---- write y (split) in [B,T,C] ----
    float i0 = 1.0f/l0, i1 = 1.0f/l1;
    int b = bh>>4, h = bh&15;
    int t0 = q0 + wid*16 + (lane>>2);
#pragma unroll
    for (int j=0;j<16;j++){
        int d = j*8 + (lane&3)*2;
        {
            float v0 = acc[j][0]*i0, v1 = acc[j][1]*i0;
            bf16 h0,L0,h1,L1; split1(v0,h0,L0); split1(v1,h1,L1);
            size_t o = ((size_t)(b*TT + t0))*CC + h*HD + d;
            *(bf162*)&g_yhi[o] = __halves2bfloat162(h0,h1);
            *(bf162*)&g_ylo[o] = __halves2bfloat162(L0,L1);
        }
        {
            float v0 = acc[j][2]*i1, v1 = acc[j][3]*i1;
            bf16 h0,L0,h1,L1; split1(v0,h0,L0); split1(v1,h1,L1);
            size_t o = ((size_t)(b*TT + t0 + 8))*CC + h*HD + d;
            *(bf162*)&g_yhi[o] = __halves2bfloat162(h0,h1);
            *(bf162*)&g_ylo[o] = __halves2bfloat162(L0,L1);
        }
    }
}

// ---- launch ----
extern "C" void kernel_launch(void* const* d_in, const int* in_sizes, int n_in,
                              void* d_out, int out_size)
{
    const float* x  = (const float*)d_in[0];
    const float* wq = (const float*)d_in[1];
    const float* wk = (const float*)d_in[2];
    const float* wv = (const float*)d_in[3];
    const float* wo = (const float*)d_in[4];
    float* out = (float*)d_out;

    cudaFuncSetAttribute(tc_gemm<0>, cudaFuncAttributeMaxDynamicSharedMemorySize, SMEM_DYN);
    cudaFuncSetAttribute(tc_gemm<1>, cudaFuncAttributeMaxDynamicSharedMemorySize, SMEM_DYN);
    cudaFuncSetAttribute(flash_k,   cudaFuncAttributeMaxDynamicSharedMemorySize, FS_SMEM);

    split_x<<<MTOT*CC/1024, 256>>>(x);
    split_w<<<dim3(CC*CC/1024, 4), 256>>>(wq, wk, wv, wo);

    tc_gemm<0><<<dim3(16,32,3), 128, SMEM_DYN>>>(nullptr);  // Q,K,V^T
    flash_k<<<dim3(TT/64, BHH), 128, FS_SMEM>>>();           // attention -> y split
    tc_gemm<1><<<dim3(16,32), 128, SMEM_DYN>>>(out);         // out-proj
}

// round 10
// speedup vs baseline: 1.6364x; 1.3994x over previous
#include <cuda_runtime.h>
#include <cuda_fp16.h>
#include <cstdint>

#define BD 2
#define TT 2048
#define CC 2048
#define NH 16
#define HD 128
#define MTOT (BD*TT)
#define BHH (BD*NH)
typedef __half f16;
typedef __half2 f162;

// A-side operands need hi only (2-pass keeps Ah*Bh + Ah*Bl)
__device__ f16 g_xh[MTOT*CC];
__device__ f16 g_wh[4][CC*CC], g_wl[4][CC*CC];
__device__ f16 g_qh[BHH*TT*HD];
__device__ f16 g_kh[BHH*TT*HD], g_kl[BHH*TT*HD];
__device__ f16 g_vth[BHH*HD*TT], g_vtl[BHH*HD*TT];
__device__ f16 g_yh[MTOT*CC];

// ---- helpers ----
__device__ __forceinline__ uint32_t su32(const void* p){
    uint32_t a; asm("{.reg .u64 t; cvta.to.shared.u64 t,%1; cvt.u32.u64 %0,t;}":"=r"(a):"l"(p)); return a;
}
#define CP_ASYNC16(s,g) asm volatile("cp.async.cg.shared.global [%0], [%1], 16;" ::"r"(s),"l"(g))
#define CP_COMMIT() asm volatile("cp.async.commit_group;" ::: "memory")
#define LDSM4(r0,r1,r2,r3,addr) \
    asm volatile("ldmatrix.sync.aligned.m8n8.x4.shared.b16 {%0,%1,%2,%3},[%4];" \
                 :"=r"(r0),"=r"(r1),"=r"(r2),"=r"(r3):"r"(addr))

__device__ __forceinline__ void mma16816(float* d, const uint32_t* a, const uint32_t* b){
    asm volatile("mma.sync.aligned.m16n8k16.row.col.f32.f16.f16.f32 "
        "{%0,%1,%2,%3},{%4,%5,%6,%7},{%8,%9},{%0,%1,%2,%3};"
        : "+f"(d[0]),"+f"(d[1]),"+f"(d[2]),"+f"(d[3])
        : "r"(a[0]),"r"(a[1]),"r"(a[2]),"r"(a[3]),"r"(b[0]),"r"(b[1]));
}

__device__ __forceinline__ void split1(float v, f16& h, f16& l){
    h = __float2half(v); l = __float2half(v - __half2float(h));
}
__device__ __forceinline__ uint32_t pack2(float x, float y){
    f162 t = __halves2half2(__float2half(x), __float2half(y));
    return *(uint32_t*)&t;
}

// ---- conversions ----
__global__ __launch_bounds__(256) void split_x(const float* __restrict__ s){
    int i = blockIdx.x*256 + threadIdx.x;
    float4 v = ((const float4*)s)[i];
    ((f162*)g_xh)[2*i  ] = __halves2half2(__float2half(v.x), __float2half(v.y));
    ((f162*)g_xh)[2*i+1] = __halves2half2(__float2half(v.z), __float2half(v.w));
}
__global__ __launch_bounds__(256) void split_w(const float* __restrict__ w0,
                                               const float* __restrict__ w1,
                                               const float* __restrict__ w2,
                                               const float* __restrict__ w3){
    int wi = blockIdx.y;
    const float* s = (wi==0)?w0:(wi==1)?w1:(wi==2)?w2:w3;
    int i = blockIdx.x*256 + threadIdx.x;
    float4 v = ((const float4*)s)[i];
    f16 h0,l0,h1,l1,h2,l2,h3,l3;
    split1(v.x,h0,l0); split1(v.y,h1,l1); split1(v.z,h2,l2); split1(v.w,h3,l3);
    ((f162*)g_wh[wi])[2*i  ] = __halves2half2(h0,h1);
    ((f162*)g_wh[wi])[2*i+1] = __halves2half2(h2,h3);
    ((f162*)g_wl[wi])[2*i  ] = __halves2half2(l0,l1);
    ((f162*)g_wl[wi])[2*i+1] = __halves2half2(l2,l3);
}

// ---- warp-MMA GEMM: 128x128 tile, 4 warps (64x64), BK=64, 2-pass fp16 ----
// MODE 0: QKV (z: 0=Q scaled, 1=K, 2=V^T).  MODE 1: out-proj.
#define BK 64
#define AS 72
#define TILE_B (128*AS*2)
#define SMEM_DYN (4*TILE_B)

template<int MODE>
__global__ __launch_bounds__(128, 2) void tc_gemm(float* __restrict__ outf)
{
    extern __shared__ f16 smem[];
    uint32_t sb = su32(smem);
    const int tid = threadIdx.x, wid = tid>>5, lane = tid&31;
    const int wm = wid&1, wn = wid>>1;
    const int n0 = blockIdx.x*128, m0 = blockIdx.y*128, z = blockIdx.z;

    const f16 *Ah,*Bh,*Bl;
    if (MODE==0){ Ah=g_xh; Bh=g_wh[z]; Bl=g_wl[z]; }
    else        { Ah=g_yh; Bh=g_wh[3]; Bl=g_wl[3]; }
    const int K = CC, Kp = K/BK, NC = 2*Kp;

    auto load_chunk = [&](int c, int b){
        int pass = c/Kp, kk = (c - pass*Kp)*BK;
        const f16* Bp = pass ? Bl : Bh;
        uint32_t sa = sb + b*TILE_B;
        uint32_t sB = sb + 2*TILE_B + b*TILE_B;
#pragma unroll
        for (int j=0;j<8;j++){
            int lin = j*128+tid, row = lin>>3, c16 = lin&7;
            CP_ASYNC16(sa + row*(AS*2) + c16*16, Ah + (size_t)(m0+row)*K + kk + c16*8);
        }
#pragma unroll
        for (int j=0;j<8;j++){
            int lin = j*128+tid, row = lin>>3, c16 = lin&7;
            CP_ASYNC16(sB + row*(AS*2) + c16*16, Bp + (size_t)(n0+row)*K + kk + c16*8);
        }
        CP_COMMIT();
    };

    float acc[4][8][4];
#pragma unroll
    for (int mi=0;mi<4;mi++)
#pragma unroll
        for (int ni=0;ni<8;ni++)
#pragma unroll
            for (int r=0;r<4;r++) acc[mi][ni][r] = 0.0f;

    load_chunk(0,0);
    for (int c=0;c<NC;c++){
        if (c+1<NC){ load_chunk(c+1,(c+1)&1); asm volatile("cp.async.wait_group 1;":::"memory"); }
        else asm volatile("cp.async.wait_group 0;":::"memory");
        __syncthreads();
        uint32_t sa = sb + (c&1)*TILE_B;
        uint32_t sB = sb + 2*TILE_B + (c&1)*TILE_B;
#pragma unroll
        for (int ks=0;ks<BK;ks+=16){
            uint32_t af[4][4], bfr[8][2];
#pragma unroll
            for (int mi=0;mi<4;mi++){
                int r = wm*64 + mi*16 + (lane&15);
                uint32_t addr = sa + r*(AS*2) + (ks + ((lane>>4)<<3))*2;
                LDSM4(af[mi][0],af[mi][1],af[mi][2],af[mi][3], addr);
            }
#pragma unroll
            for (int g=0;g<4;g++){
                int nr = wn*64 + g*16 + ((lane>>4)<<3) + (lane&7);
                uint32_t addr = sB + nr*(AS*2) + (ks + ((lane>>3)&1)*8)*2;
                uint32_t r0,r1,r2,r3;
                LDSM4(r0,r1,r2,r3, addr);
                bfr[2*g][0]=r0; bfr[2*g][1]=r1; bfr[2*g+1][0]=r2; bfr[2*g+1][1]=r3;
            }
#pragma unroll
            for (int mi=0;mi<4;mi++)
#pragma unroll
                for (int ni=0;ni<8;ni++)
                    mma16816(acc[mi][ni], af[mi], bfr[ni]);
        }
        __syncthreads();
    }

    const int lrow = lane>>2, lcol = (lane&3)*2;
#pragma unroll
    for (int mi=0;mi<4;mi++){
#pragma unroll
        for (int ni=0;ni<8;ni++){
            int cw = wn*64 + ni*8 + lcol;
            int n  = n0 + cw;
#pragma unroll
            for (int half=0; half<2; half++){
                int m = m0 + wm*64 + mi*16 + lrow + half*8;
                float v0 = acc[mi][ni][2*half], v1 = acc[mi][ni][2*half+1];
                if (MODE==0){
                    int b = m>>11, t = m&(TT-1), h = blockIdx.x, d = cw;
                    if (z==0){
                        v0 *= 0.08838834764831845f; v1 *= 0.08838834764831845f;
                        size_t o = ((size_t)(b*NH+h)*TT + t)*HD + d;
                        *(f162*)&g_qh[o] = __halves2half2(__float2half(v0), __float2half(v1));
                    } else if (z==1){
                        f16 h0,l0,h1,l1; split1(v0,h0,l0); split1(v1,h1,l1);
                        size_t o = ((size_t)(b*NH+h)*TT + t)*HD + d;
                        *(f162*)&g_kh[o] = __halves2half2(h0,h1);
                        *(f162*)&g_kl[o] = __halves2half2(l0,l1);
                    } else {
                        f16 h0,l0,h1,l1; split1(v0,h0,l0); split1(v1,h1,l1);
                        size_t o = ((size_t)(b*NH+h)*HD + d)*TT + t;
                        g_vth[o] = h0; g_vtl[o] = l0;
                        g_vth[o+TT] = h1; g_vtl[o+TT] = l1;
                    }
                } else {
                    *(float2*)&outf[(size_t)m*CC + n] = make_float2(v0, v1);
                }
            }
        }
    }
}

// ---- fused flash attention: 64q x 64k tiles, 4 warps, 2-pass fp16 ----
#define SKQ 136               // Q/K row stride in halves
#define SKV 72                // V row stride in halves
#define FQH 0
#define FKH (64*SKQ*2)
#define FKL (2*64*SKQ*2)
#define FVH (3*64*SKQ*2)
#define FVL (3*64*SKQ*2 + 128*SKV*2)
#define FS_SMEM (3*64*SKQ*2 + 2*128*SKV*2)   // 89088

__global__ __launch_bounds__(128, 2) void flash_k()
{
    extern __shared__ f16 fsm[];
    uint32_t sb = su32(fsm);
    const uint32_t QH=sb+FQH, KH=sb+FKH, KL=sb+FKL, VH=sb+FVH, VL=sb+FVL;
    const int tid = threadIdx.x, wid = tid>>5, lane = tid&31;
    const int bh = blockIdx.y, q0 = blockIdx.x*64;

    const f16* Qh = g_qh + ((size_t)bh*TT + q0)*HD;
    const f16* Kh = g_kh + (size_t)bh*TT*HD;
    const f16* Kl = g_kl + (size_t)bh*TT*HD;
    const f16* Vh = g_vth + (size_t)bh*HD*TT;
    const f16* Vl = g_vtl + (size_t)bh*HD*TT;

    auto ldQK = [&](uint32_t dst, const f16* src){
#pragma unroll
        for (int j=0;j<8;j++){
            int lin = j*128+tid, row = lin>>4, c = lin&15;
            CP_ASYNC16(dst + row*(SKQ*2) + c*16, src + (size_t)row*HD + c*8);
        }
    };
    auto ldV = [&](uint32_t dst, const f16* src, int coloff){
#pragma unroll
        for (int j=0;j<8;j++){
            int lin = j*128+tid, row = lin>>3, c = lin&7;
            CP_ASYNC16(dst + row*(SKV*2) + c*16, src + (size_t)row*TT + coloff + c*8);
        }
    };

    ldQK(QH, Qh);
    CP_COMMIT();

    float acc[16][4];
#pragma unroll
    for (int j=0;j<16;j++){ acc[j][0]=0;acc[j][1]=0;acc[j][2]=0;acc[j][3]=0; }
    float m0=-1e30f, m1=-1e30f, l0=0.0f, l1=0.0f;

    for (int kt=0; kt<TT/64; kt++){
        __syncthreads();
        ldQK(KH, Kh + (size_t)kt*64*HD);
        ldQK(KL, Kl + (size_t)kt*64*HD);
        ldV(VH, Vh, kt*64);
        ldV(VL, Vl, kt*64);
        CP_COMMIT();
        asm volatile("cp.async.wait_group 0;":::"memory");
        __syncthreads();

        // ---- S = QK^T (2-pass: Qh*Kh + Qh*Kl) ----
        float S[8][4];
#pragma unroll
        for (int j=0;j<8;j++){ S[j][0]=0;S[j][1]=0;S[j][2]=0;S[j][3]=0; }
#pragma unroll
        for (int ks=0;ks<8;ks++){
            uint32_t qh[4];
            int ar = wid*16 + (lane&15);
            uint32_t acol = (ks*16 + ((lane>>4)<<3))*2;
            LDSM4(qh[0],qh[1],qh[2],qh[3], QH + ar*(SKQ*2) + acol);
#pragma unroll
            for (int g=0;g<4;g++){
                int nr = g*16 + ((lane>>4)<<3) + (lane&7);
                uint32_t bcol = (ks*16 + ((lane>>3)&1)*8)*2;
                uint32_t h0,h1,h2,h3, e0,e1,e2,e3;
                LDSM4(h0,h1,h2,h3, KH + nr*(SKQ*2) + bcol);
                LDSM4(e0,e1,e2,e3, KL + nr*(SKQ*2) + bcol);
                uint32_t bh0[2]={h0,h1}, bh1[2]={h2,h3}, bl0[2]={e0,e1}, bl1[2]={e2,e3};
                mma16816(S[2*g],   qh, bh0); mma16816(S[2*g+1], qh, bh1);
                mma16816(S[2*g],   qh, bl0); mma16816(S[2*g+1], qh, bl1);
            }
        }

        // ---- online softmax ----
        float mx0=-1e30f, mx1=-1e30f;
#pragma unroll
        for (int j=0;j<8;j++){
            mx0 = fmaxf(mx0, fmaxf(S[j][0],S[j][1]));
            mx1 = fmaxf(mx1, fmaxf(S[j][2],S[j][3]));
        }
        mx0 = fmaxf(mx0, __shfl_xor_sync(~0u,mx0,1)); mx0 = fmaxf(mx0, __shfl_xor_sync(~0u,mx0,2));
        mx1 = fmaxf(mx1, __shfl_xor_sync(~0u,mx1,1)); mx1 = fmaxf(mx1, __shfl_xor_sync(~0u,mx1,2));
        float mn0 = fmaxf(m0,mx0), mn1 = fmaxf(m1,mx1);
        float c0 = __expf(m0-mn0), c1 = __expf(m1-mn1);
        float ls0=0.0f, ls1=0.0f;
#pragma unroll
        for (int j=0;j<8;j++){
            S[j][0]=__expf(S[j][0]-mn0); S[j][1]=__expf(S[j][1]-mn0); ls0 += S[j][0]+S[j][1];
            S[j][2]=__expf(S[j][2]-mn1); S[j][3]=__expf(S[j][3]-mn1); ls1 += S[j][2]+S[j][3];
        }
        ls0 += __shfl_xor_sync(~0u,ls0,1); ls0 += __shfl_xor_sync(~0u,ls0,2);
        ls1 += __shfl_xor_sync(~0u,ls1,1); ls1 += __shfl_xor_sync(~0u,ls1,2);
        l0 = l0*c0 + ls0; l1 = l1*c1 + ls1; m0 = mn0; m1 = mn1;
#pragma unroll
        for (int j=0;j<16;j++){ acc[j][0]*=c0; acc[j][1]*=c0; acc[j][2]*=c1; acc[j][3]*=c1; }

        // ---- acc += P V (2-pass: Ph*Vh + Ph*Vl) ----
#pragma unroll
        for (int ks=0;ks<4;ks++){
            uint32_t ph[4];
            ph[0]=pack2(S[2*ks][0],  S[2*ks][1]);   ph[1]=pack2(S[2*ks][2],  S[2*ks][3]);
            ph[2]=pack2(S[2*ks+1][0],S[2*ks+1][1]); ph[3]=pack2(S[2*ks+1][2],S[2*ks+1][3]);
#pragma unroll
            for (int g=0;g<8;g++){
                int nr = g*16 + ((lane>>4)<<3) + (lane&7);
                uint32_t bcol = (ks*16 + ((lane>>3)&1)*8)*2;
                uint32_t h0,h1,h2,h3, e0,e1,e2,e3;
                LDSM4(h0,h1,h2,h3, VH + nr*(SKV*2) + bcol);
                LDSM4(e0,e1,e2,e3, VL + nr*(SKV*2) + bcol);
                uint32_t bh0[2]={h0,h1}, bh1[2]={h2,h3}, bl0[2]={e0,e1}, bl1[2]={e2,e3};
                mma16816(acc[2*g],   ph, bh0); mma16816(acc[2*g+1], ph, bh1);
                mma16816(acc[2*g],   ph, bl0); mma16816(acc[2*g+1], ph, bl1);
            }
        }
    }

    // ---- write y (fp16 hi) in [B,T,C] ----
    float i0 = 1.0f/l0, i1 = 1.0f/l1;
    int b = bh>>4, h = bh&15;
    int t0 = q0 + wid*16 + (lane>>2);
#pragma unroll
    for (int j=0;j<16;j++){
        int d = j*8 + (lane&3)*2;
        {
            size_t o = ((size_t)(b*TT + t0))*CC + h*HD + d;
            *(f162*)&g_yh[o] = __halves2half2(__float2half(acc[j][0]*i0), __float2half(acc[j][1]*i0));
        }
        {
            size_t o = ((size_t)(b*TT + t0 + 8))*CC + h*HD + d;
            *(f162*)&g_yh[o] = __halves2half2(__float2half(acc[j][2]*i1), __float2half(acc[j][3]*i1));
        }
    }
}

// ---- launch ----
extern "C" void kernel_launch(void* const* d_in, const int* in_sizes, int n_in,
                              void* d_out, int out_size)
{
    const float* x  = (const float*)d_in[0];
    const float* wq = (const float*)d_in[1];
    const float* wk = (const float*)d_in[2];
    const float* wv = (const float*)d_in[3];
    const float* wo = (const float*)d_in[4];
    float* out = (float*)d_out;

    cudaFuncSetAttribute(tc_gemm<0>, cudaFuncAttributeMaxDynamicSharedMemorySize, SMEM_DYN);
    cudaFuncSetAttribute(tc_gemm<1>, cudaFuncAttributeMaxDynamicSharedMemorySize, SMEM_DYN);
    cudaFuncSetAttribute(flash_k,   cudaFuncAttributeMaxDynamicSharedMemorySize, FS_SMEM);

    split_x<<<MTOT*CC/1024, 256>>>(x);
    split_w<<<dim3(CC*CC/1024, 4), 256>>>(wq, wk, wv, wo);

    tc_gemm<0><<<dim3(16,32,3), 128, SMEM_DYN>>>(nullptr);  // Q,K,V^T
    flash_k<<<dim3(TT/64, BHH), 128, FS_SMEM>>>();           // attention -> y fp16
    tc_gemm<1><<<dim3(16,32), 128, SMEM_DYN>>>(out);         // out-proj
}

// round 13
// speedup vs baseline: 2.2051x; 1.3475x over previous
#include <cuda_runtime.h>
#include <cuda_fp16.h>
#include <cstdint>

#define BD 2
#define TT 2048
#define CC 2048
#define NH 16
#define HD 128
#define MTOT (BD*TT)
#define BHH (BD*NH)
typedef __half f16;
typedef __half2 f162;

__device__ f16 g_xh[MTOT*CC];
__device__ f16 g_wh[4][CC*CC], g_wl[2][CC*CC];   // lo only for wq, wk
__device__ f16 g_qh[BHH*TT*HD];
__device__ f16 g_kh[BHH*TT*HD], g_kl[BHH*TT*HD];
__device__ f16 g_vth[BHH*HD*TT];
__device__ f16 g_yh[MTOT*CC];

// ---- helpers ----
__device__ __forceinline__ uint32_t su32(const void* p){
    uint32_t a; asm("{.reg .u64 t; cvta.to.shared.u64 t,%1; cvt.u32.u64 %0,t;}":"=r"(a):"l"(p)); return a;
}
#define CP_ASYNC16(s,g) asm volatile("cp.async.cg.shared.global [%0], [%1], 16;" ::"r"(s),"l"(g))
#define CP_COMMIT() asm volatile("cp.async.commit_group;" ::: "memory")
#define LDSM4(r0,r1,r2,r3,addr) \
    asm volatile("ldmatrix.sync.aligned.m8n8.x4.shared.b16 {%0,%1,%2,%3},[%4];" \
                 :"=r"(r0),"=r"(r1),"=r"(r2),"=r"(r3):"r"(addr))

__device__ __forceinline__ void mma16816(float* d, const uint32_t* a, const uint32_t* b){
    asm volatile("mma.sync.aligned.m16n8k16.row.col.f32.f16.f16.f32 "
        "{%0,%1,%2,%3},{%4,%5,%6,%7},{%8,%9},{%0,%1,%2,%3};"
        : "+f"(d[0]),"+f"(d[1]),"+f"(d[2]),"+f"(d[3])
        : "r"(a[0]),"r"(a[1]),"r"(a[2]),"r"(a[3]),"r"(b[0]),"r"(b[1]));
}

__device__ __forceinline__ void split1(float v, f16& h, f16& l){
    h = __float2half(v); l = __float2half(v - __half2float(h));
}
__device__ __forceinline__ uint32_t pack2(float x, float y){
    f162 t = __halves2half2(__float2half(x), __float2half(y));
    return *(uint32_t*)&t;
}

// ---- conversions ----
__global__ __launch_bounds__(256) void split_x(const float* __restrict__ s){
    int i = blockIdx.x*256 + threadIdx.x;
    float4 v = ((const float4*)s)[i];
    ((f162*)g_xh)[2*i  ] = __halves2half2(__float2half(v.x), __float2half(v.y));
    ((f162*)g_xh)[2*i+1] = __halves2half2(__float2half(v.z), __float2half(v.w));
}
// wi 0..3 = wq,wk,wv,wo. lo stored only for wq,wk.
__global__ __launch_bounds__(256) void split_w(const float* __restrict__ w0,
                                               const float* __restrict__ w1,
                                               const float* __restrict__ w2,
                                               const float* __restrict__ w3){
    int wi = blockIdx.y;
    const float* s = (wi==0)?w0:(wi==1)?w1:(wi==2)?w2:w3;
    int i = blockIdx.x*256 + threadIdx.x;
    float4 v = ((const float4*)s)[i];
    f16 h0,l0,h1,l1,h2,l2,h3,l3;
    split1(v.x,h0,l0); split1(v.y,h1,l1); split1(v.z,h2,l2); split1(v.w,h3,l3);
    ((f162*)g_wh[wi])[2*i  ] = __halves2half2(h0,h1);
    ((f162*)g_wh[wi])[2*i+1] = __halves2half2(h2,h3);
    if (wi < 2){
        ((f162*)g_wl[wi])[2*i  ] = __halves2half2(l0,l1);
        ((f162*)g_wl[wi])[2*i+1] = __halves2half2(l2,l3);
    }
}

// ---- warp-MMA GEMM: 128x128 tile, 4 warps (64x64), BK=64 ----
// MODE 0: QKV (z: 0=Q scaled 2-pass, 1=K 2-pass, 2=V^T 1-pass). MODE 1: out-proj 1-pass.
#define BK 64
#define AS 72
#define TILE_B (128*AS*2)
#define SMEM_DYN (4*TILE_B)

template<int MODE>
__global__ __launch_bounds__(128, 2) void tc_gemm(float* __restrict__ outf)
{
    extern __shared__ f16 smem[];
    uint32_t sb = su32(smem);
    const int tid = threadIdx.x, wid = tid>>5, lane = tid&31;
    const int wm = wid&1, wn = wid>>1;
    const int n0 = blockIdx.x*128, m0 = blockIdx.y*128, z = blockIdx.z;

    const f16 *Ah,*Bh,*Bl;
    if (MODE==0){ Ah=g_xh; Bh=g_wh[z]; Bl=(z<2)?g_wl[z]:g_wh[z]; }
    else        { Ah=g_yh; Bh=g_wh[3]; Bl=g_wh[3]; }
    const int K = CC, Kp = K/BK;
    const int NPASS = (MODE==1 || z==2) ? 1 : 2;
    const int NC = NPASS*Kp;

    auto load_chunk = [&](int c, int b){
        int pass = c/Kp, kk = (c - pass*Kp)*BK;
        const f16* Bp = pass ? Bl : Bh;
        uint32_t sa = sb + b*TILE_B;
        uint32_t sB = sb + 2*TILE_B + b*TILE_B;
#pragma unroll
        for (int j=0;j<8;j++){
            int lin = j*128+tid, row = lin>>3, c16 = lin&7;
            CP_ASYNC16(sa + row*(AS*2) + c16*16, Ah + (size_t)(m0+row)*K + kk + c16*8);
        }
#pragma unroll
        for (int j=0;j<8;j++){
            int lin = j*128+tid, row = lin>>3, c16 = lin&7;
            CP_ASYNC16(sB + row*(AS*2) + c16*16, Bp + (size_t)(n0+row)*K + kk + c16*8);
        }
        CP_COMMIT();
    };

    float acc[4][8][4];
#pragma unroll
    for (int mi=0;mi<4;mi++)
#pragma unroll
        for (int ni=0;ni<8;ni++)
#pragma unroll
            for (int r=0;r<4;r++) acc[mi][ni][r] = 0.0f;

    load_chunk(0,0);
    for (int c=0;c<NC;c++){
        if (c+1<NC){ load_chunk(c+1,(c+1)&1); asm volatile("cp.async.wait_group 1;":::"memory"); }
        else asm volatile("cp.async.wait_group 0;":::"memory");
        __syncthreads();
        uint32_t sa = sb + (c&1)*TILE_B;
        uint32_t sB = sb + 2*TILE_B + (c&1)*TILE_B;
#pragma unroll
        for (int ks=0;ks<BK;ks+=16){
            uint32_t af[4][4], bfr[8][2];
#pragma unroll
            for (int mi=0;mi<4;mi++){
                int r = wm*64 + mi*16 + (lane&15);
                uint32_t addr = sa + r*(AS*2) + (ks + ((lane>>4)<<3))*2;
                LDSM4(af[mi][0],af[mi][1],af[mi][2],af[mi][3], addr);
            }
#pragma unroll
            for (int g=0;g<4;g++){
                int nr = wn*64 + g*16 + ((lane>>4)<<3) + (lane&7);
                uint32_t addr = sB + nr*(AS*2) + (ks + ((lane>>3)&1)*8)*2;
                uint32_t r0,r1,r2,r3;
                LDSM4(r0,r1,r2,r3, addr);
                bfr[2*g][0]=r0; bfr[2*g][1]=r1; bfr[2*g+1][0]=r2; bfr[2*g+1][1]=r3;
            }
#pragma unroll
            for (int mi=0;mi<4;mi++)
#pragma unroll
                for (int ni=0;ni<8;ni++)
                    mma16816(acc[mi][ni], af[mi], bfr[ni]);
        }
        __syncthreads();
    }

    const int lrow = lane>>2, lcol = (lane&3)*2;
#pragma unroll
    for (int mi=0;mi<4;mi++){
#pragma unroll
        for (int ni=0;ni<8;ni++){
            int cw = wn*64 + ni*8 + lcol;
            int n  = n0 + cw;
#pragma unroll
            for (int half=0; half<2; half++){
                int m = m0 + wm*64 + mi*16 + lrow + half*8;
                float v0 = acc[mi][ni][2*half], v1 = acc[mi][ni][2*half+1];
                if (MODE==0){
                    int b = m>>11, t = m&(TT-1), h = blockIdx.x, d = cw;
                    if (z==0){
                        v0 *= 0.08838834764831845f; v1 *= 0.08838834764831845f;
                        size_t o = ((size_t)(b*NH+h)*TT + t)*HD + d;
                        *(f162*)&g_qh[o] = __halves2half2(__float2half(v0), __float2half(v1));
                    } else if (z==1){
                        f16 h0,l0,h1,l1; split1(v0,h0,l0); split1(v1,h1,l1);
                        size_t o = ((size_t)(b*NH+h)*TT + t)*HD + d;
                        *(f162*)&g_kh[o] = __halves2half2(h0,h1);
                        *(f162*)&g_kl[o] = __halves2half2(l0,l1);
                    } else {
                        size_t o = ((size_t)(b*NH+h)*HD + d)*TT + t;
                        g_vth[o] = __float2half(v0);
                        g_vth[o+TT] = __float2half(v1);
                    }
                } else {
                    *(float2*)&outf[(size_t)m*CC + n] = make_float2(v0, v1);
                }
            }
        }
    }
}

// ---- fused flash attention: 64q x 64k tiles, 4 warps, 3 CTAs/SM ----
// S = Qh*(Kh+Kl) 2-pass; PV = Ph*Vh 1-pass.
#define SKQ 136
#define SKV 72
#define FQH 0
#define FKH (64*SKQ*2)
#define FKL (2*64*SKQ*2)
#define FVH (3*64*SKQ*2)
#define FS_SMEM (3*64*SKQ*2 + 128*SKV*2)   // 70656

__global__ __launch_bounds__(128, 3) void flash_k()
{
    extern __shared__ f16 fsm[];
    uint32_t sb = su32(fsm);
    const uint32_t QH=sb+FQH, KH=sb+FKH, KL=sb+FKL, VH=sb+FVH;
    const int tid = threadIdx.x, wid = tid>>5, lane = tid&31;
    const int bh = blockIdx.y, q0 = blockIdx.x*64;

    const f16* Qh = g_qh + ((size_t)bh*TT + q0)*HD;
    const f16* Kh = g_kh + (size_t)bh*TT*HD;
    const f16* Kl = g_kl + (size_t)bh*TT*HD;
    const f16* Vh = g_vth + (size_t)bh*HD*TT;

    auto ldQK = [&](uint32_t dst, const f16* src){
#pragma unroll
        for (int j=0;j<8;j++){
            int lin = j*128+tid, row = lin>>4, c = lin&15;
            CP_ASYNC16(dst + row*(SKQ*2) + c*16, src + (size_t)row*HD + c*8);
        }
    };
    auto ldV = [&](uint32_t dst, const f16* src, int coloff){
#pragma unroll
        for (int j=0;j<8;j++){
            int lin = j*128+tid, row = lin>>3, c = lin&7;
            CP_ASYNC16(dst + row*(SKV*2) + c*16, src + (size_t)row*TT + coloff + c*8);
        }
    };

    ldQK(QH, Qh);
    CP_COMMIT();

    float acc[16][4];
#pragma unroll
    for (int j=0;j<16;j++){ acc[j][0]=0;acc[j][1]=0;acc[j][2]=0;acc[j][3]=0; }
    float m0=-1e30f, m1=-1e30f, l0=0.0f, l1=0.0f;

    for (int kt=0; kt<TT/64; kt++){
        __syncthreads();
        ldQK(KH, Kh + (size_t)kt*64*HD);
        ldQK(KL, Kl + (size_t)kt*64*HD);
        ldV(VH, Vh, kt*64);
        CP_COMMIT();
        asm volatile("cp.async.wait_group 0;":::"memory");
        __syncthreads();

        // ---- S = QK^T (2-pass) ----
        float S[8][4];
#pragma unroll
        for (int j=0;j<8;j++){ S[j][0]=0;S[j][1]=0;S[j][2]=0;S[j][3]=0; }
#pragma unroll
        for (int ks=0;ks<8;ks++){
            uint32_t qh[4];
            int ar = wid*16 + (lane&15);
            uint32_t acol = (ks*16 + ((lane>>4)<<3))*2;
            LDSM4(qh[0],qh[1],qh[2],qh[3], QH + ar*(SKQ*2) + acol);
#pragma unroll
            for (int g=0;g<4;g++){
                int nr = g*16 + ((lane>>4)<<3) + (lane&7);
                uint32_t bcol = (ks*16 + ((lane>>3)&1)*8)*2;
                uint32_t h0,h1,h2,h3, e0,e1,e2,e3;
                LDSM4(h0,h1,h2,h3, KH + nr*(SKQ*2) + bcol);
                LDSM4(e0,e1,e2,e3, KL + nr*(SKQ*2) + bcol);
                uint32_t bh0[2]={h0,h1}, bh1[2]={h2,h3}, bl0[2]={e0,e1}, bl1[2]={e2,e3};
                mma16816(S[2*g],   qh, bh0); mma16816(S[2*g+1], qh, bh1);
                mma16816(S[2*g],   qh, bl0); mma16816(S[2*g+1], qh, bl1);
            }
        }

        // ---- online softmax ----
        float mx0=-1e30f, mx1=-1e30f;
#pragma unroll
        for (int j=0;j<8;j++){
            mx0 = fmaxf(mx0, fmaxf(S[j][0],S[j][1]));
            mx1 = fmaxf(mx1, fmaxf(S[j][2],S[j][3]));
        }
        mx0 = fmaxf(mx0, __shfl_xor_sync(~0u,mx0,1)); mx0 = fmaxf(mx0, __shfl_xor_sync(~0u,mx0,2));
        mx1 = fmaxf(mx1, __shfl_xor_sync(~0u,mx1,1)); mx1 = fmaxf(mx1, __shfl_xor_sync(~0u,mx1,2));
        float mn0 = fmaxf(m0,mx0), mn1 = fmaxf(m1,mx1);
        float c0 = __expf(m0-mn0), c1 = __expf(m1-mn1);
        float ls0=0.0f, ls1=0.0f;
#pragma unroll
        for (int j=0;j<8;j++){
            S[j][0]=__expf(S[j][0]-mn0); S[j][1]=__expf(S[j][1]-mn0); ls0 += S[j][0]+S[j][1];
            S[j][2]=__expf(S[j][2]-mn1); S[j][3]=__expf(S[j][3]-mn1); ls1 += S[j][2]+S[j][3];
        }
        ls0 += __shfl_xor_sync(~0u,ls0,1); ls0 += __shfl_xor_sync(~0u,ls0,2);
        ls1 += __shfl_xor_sync(~0u,ls1,1); ls1 += __shfl_xor_sync(~0u,ls1,2);
        l0 = l0*c0 + ls0; l1 = l1*c1 + ls1; m0 = mn0; m1 = mn1;
#pragma unroll
        for (int j=0;j<16;j++){ acc[j][0]*=c0; acc[j][1]*=c0; acc[j][2]*=c1; acc[j][3]*=c1; }

        // ---- acc += P V (1-pass) ----
#pragma unroll
        for (int ks=0;ks<4;ks++){
            uint32_t ph[4];
            ph[0]=pack2(S[2*ks][0],  S[2*ks][1]);   ph[1]=pack2(S[2*ks][2],  S[2*ks][3]);
            ph[2]=pack2(S[2*ks+1][0],S[2*ks+1][1]); ph[3]=pack2(S[2*ks+1][2],S[2*ks+1][3]);
#pragma unroll
            for (int g=0;g<8;g++){
                int nr = g*16 + ((lane>>4)<<3) + (lane&7);
                uint32_t bcol = (ks*16 + ((lane>>3)&1)*8)*2;
                uint32_t h0,h1,h2,h3;
                LDSM4(h0,h1,h2,h3, VH + nr*(SKV*2) + bcol);
                uint32_t bh0[2]={h0,h1}, bh1[2]={h2,h3};
                mma16816(acc[2*g],   ph, bh0); mma16816(acc[2*g+1], ph, bh1);
            }
        }
    }

    // ---- write y (fp16) in [B,T,C] ----
    float i0 = 1.0f/l0, i1 = 1.0f/l1;
    int b = bh>>4, h = bh&15;
    int t0 = q0 + wid*16 + (lane>>2);
#pragma unroll
    for (int j=0;j<16;j++){
        int d = j*8 + (lane&3)*2;
        {
            size_t o = ((size_t)(b*TT + t0))*CC + h*HD + d;
            *(f162*)&g_yh[o] = __halves2half2(__float2half(acc[j][0]*i0), __float2half(acc[j][1]*i0));
        }
        {
            size_t o = ((size_t)(b*TT + t0 + 8))*CC + h*HD + d;
            *(f162*)&g_yh[o] = __halves2half2(__float2half(acc[j][2]*i1), __float2half(acc[j][3]*i1));
        }
    }
}

// ---- launch ----
extern "C" void kernel_launch(void* const* d_in, const int* in_sizes, int n_in,
                              void* d_out, int out_size)
{
    const float* x  = (const float*)d_in[0];
    const float* wq = (const float*)d_in[1];
    const float* wk = (const float*)d_in[2];
    const float* wv = (const float*)d_in[3];
    const float* wo = (const float*)d_in[4];
    float* out = (float*)d_out;

    cudaFuncSetAttribute(tc_gemm<0>, cudaFuncAttributeMaxDynamicSharedMemorySize, SMEM_DYN);
    cudaFuncSetAttribute(tc_gemm<1>, cudaFuncAttributeMaxDynamicSharedMemorySize, SMEM_DYN);
    cudaFuncSetAttribute(flash_k,   cudaFuncAttributeMaxDynamicSharedMemorySize, FS_SMEM);

    split_x<<<MTOT*CC/1024, 256>>>(x);
    split_w<<<dim3(CC*CC/1024, 4), 256>>>(wq, wk, wv, wo);

    tc_gemm<0><<<dim3(16,32,3), 128, SMEM_DYN>>>(nullptr);  // Q,K,V^T
    flash_k<<<dim3(TT/64, BHH), 128, FS_SMEM>>>();           // attention -> y fp16
    tc_gemm<1><<<dim3(16,32), 128, SMEM_DYN>>>(out);         // out-proj
}

// round 15
// speedup vs baseline: 2.7786x; 1.2601x over previous
#include <cuda_runtime.h>
#include <cuda_fp16.h>
#include <cstdint>

#define BD 2
#define TT 2048
#define CC 2048
#define NH 16
#define HD 128
#define MTOT (BD*TT)
#define BHH (BD*NH)
typedef __half f16;
typedef __half2 f162;

__device__ f16 g_xh[MTOT*CC];
__device__ f16 g_wh[4][CC*CC], g_wl[1][CC*CC];   // lo only for wq
__device__ f16 g_qh[BHH*TT*HD];
__device__ f16 g_kh[BHH*TT*HD];
__device__ f16 g_vth[BHH*HD*TT];
__device__ f16 g_yh[MTOT*CC];

// ---- helpers ----
__device__ __forceinline__ uint32_t su32(const void* p){
    uint32_t a; asm("{.reg .u64 t; cvta.to.shared.u64 t,%1; cvt.u32.u64 %0,t;}":"=r"(a):"l"(p)); return a;
}
#define CP_ASYNC16(s,g) asm volatile("cp.async.cg.shared.global [%0], [%1], 16;" ::"r"(s),"l"(g))
#define CP_COMMIT() asm volatile("cp.async.commit_group;" ::: "memory")
#define LDSM4(r0,r1,r2,r3,addr) \
    asm volatile("ldmatrix.sync.aligned.m8n8.x4.shared.b16 {%0,%1,%2,%3},[%4];" \
                 :"=r"(r0),"=r"(r1),"=r"(r2),"=r"(r3):"r"(addr))

__device__ __forceinline__ void mma16816(float* d, const uint32_t* a, const uint32_t* b){
    asm volatile("mma.sync.aligned.m16n8k16.row.col.f32.f16.f16.f32 "
        "{%0,%1,%2,%3},{%4,%5,%6,%7},{%8,%9},{%0,%1,%2,%3};"
        : "+f"(d[0]),"+f"(d[1]),"+f"(d[2]),"+f"(d[3])
        : "r"(a[0]),"r"(a[1]),"r"(a[2]),"r"(a[3]),"r"(b[0]),"r"(b[1]));
}

__device__ __forceinline__ void split1(float v, f16& h, f16& l){
    h = __float2half(v); l = __float2half(v - __half2float(h));
}
__device__ __forceinline__ uint32_t pack2(float x, float y){
    f162 t = __halves2half2(__float2half(x), __float2half(y));
    return *(uint32_t*)&t;
}

// ---- conversions ----
__global__ __launch_bounds__(256) void split_x(const float* __restrict__ s){
    int i = blockIdx.x*256 + threadIdx.x;
    float4 v = ((const float4*)s)[i];
    ((f162*)g_xh)[2*i  ] = __halves2half2(__float2half(v.x), __float2half(v.y));
    ((f162*)g_xh)[2*i+1] = __halves2half2(__float2half(v.z), __float2half(v.w));
}
// wi 0..3 = wq,wk,wv,wo. lo stored only for wq.
__global__ __launch_bounds__(256) void split_w(const float* __restrict__ w0,
                                               const float* __restrict__ w1,
                                               const float* __restrict__ w2,
                                               const float* __restrict__ w3){
    int wi = blockIdx.y;
    const float* s = (wi==0)?w0:(wi==1)?w1:(wi==2)?w2:w3;
    int i = blockIdx.x*256 + threadIdx.x;
    float4 v = ((const float4*)s)[i];
    f16 h0,l0,h1,l1,h2,l2,h3,l3;
    split1(v.x,h0,l0); split1(v.y,h1,l1); split1(v.z,h2,l2); split1(v.w,h3,l3);
    ((f162*)g_wh[wi])[2*i  ] = __halves2half2(h0,h1);
    ((f162*)g_wh[wi])[2*i+1] = __halves2half2(h2,h3);
    if (wi == 0){
        ((f162*)g_wl[0])[2*i  ] = __halves2half2(l0,l1);
        ((f162*)g_wl[0])[2*i+1] = __halves2half2(l2,l3);
    }
}

// ---- warp-MMA GEMM: 128x128 tile, 4 warps (64x64), BK=64 ----
// MODE 0: QKV (z: 0=Q scaled 2-pass, 1=K 1-pass, 2=V^T 1-pass). MODE 1: out-proj 1-pass.
#define BK 64
#define AS 72
#define TILE_B (128*AS*2)
#define SMEM_DYN (4*TILE_B)

template<int MODE>
__global__ __launch_bounds__(128, 2) void tc_gemm(float* __restrict__ outf)
{
    extern __shared__ f16 smem[];
    uint32_t sb = su32(smem);
    const int tid = threadIdx.x, wid = tid>>5, lane = tid&31;
    const int wm = wid&1, wn = wid>>1;
    const int n0 = blockIdx.x*128, m0 = blockIdx.y*128, z = blockIdx.z;

    const f16 *Ah,*Bh,*Bl;
    if (MODE==0){ Ah=g_xh; Bh=g_wh[z]; Bl=(z==0)?g_wl[0]:g_wh[z]; }
    else        { Ah=g_yh; Bh=g_wh[3]; Bl=g_wh[3]; }
    const int K = CC, Kp = K/BK;
    const int NPASS = (MODE==0 && z==0) ? 2 : 1;
    const int NC = NPASS*Kp;

    auto load_chunk = [&](int c, int b){
        int pass = c/Kp, kk = (c - pass*Kp)*BK;
        const f16* Bp = pass ? Bl : Bh;
        uint32_t sa = sb + b*TILE_B;
        uint32_t sB = sb + 2*TILE_B + b*TILE_B;
#pragma unroll
        for (int j=0;j<8;j++){
            int lin = j*128+tid, row = lin>>3, c16 = lin&7;
            CP_ASYNC16(sa + row*(AS*2) + c16*16, Ah + (size_t)(m0+row)*K + kk + c16*8);
        }
#pragma unroll
        for (int j=0;j<8;j++){
            int lin = j*128+tid, row = lin>>3, c16 = lin&7;
            CP_ASYNC16(sB + row*(AS*2) + c16*16, Bp + (size_t)(n0+row)*K + kk + c16*8);
        }
        CP_COMMIT();
    };

    float acc[4][8][4];
#pragma unroll
    for (int mi=0;mi<4;mi++)
#pragma unroll
        for (int ni=0;ni<8;ni++)
#pragma unroll
            for (int r=0;r<4;r++) acc[mi][ni][r] = 0.0f;

    load_chunk(0,0);
    for (int c=0;c<NC;c++){
        if (c+1<NC){ load_chunk(c+1,(c+1)&1); asm volatile("cp.async.wait_group 1;":::"memory"); }
        else asm volatile("cp.async.wait_group 0;":::"memory");
        __syncthreads();
        uint32_t sa = sb + (c&1)*TILE_B;
        uint32_t sB = sb + 2*TILE_B + (c&1)*TILE_B;
#pragma unroll
        for (int ks=0;ks<BK;ks+=16){
            uint32_t af[4][4], bfr[8][2];
#pragma unroll
            for (int mi=0;mi<4;mi++){
                int r = wm*64 + mi*16 + (lane&15);
                uint32_t addr = sa + r*(AS*2) + (ks + ((lane>>4)<<3))*2;
                LDSM4(af[mi][0],af[mi][1],af[mi][2],af[mi][3], addr);
            }
#pragma unroll
            for (int g=0;g<4;g++){
                int nr = wn*64 + g*16 + ((lane>>4)<<3) + (lane&7);
                uint32_t addr = sB + nr*(AS*2) + (ks + ((lane>>3)&1)*8)*2;
                uint32_t r0,r1,r2,r3;
                LDSM4(r0,r1,r2,r3, addr);
                bfr[2*g][0]=r0; bfr[2*g][1]=r1; bfr[2*g+1][0]=r2; bfr[2*g+1][1]=r3;
            }
#pragma unroll
            for (int mi=0;mi<4;mi++)
#pragma unroll
                for (int ni=0;ni<8;ni++)
                    mma16816(acc[mi][ni], af[mi], bfr[ni]);
        }
        __syncthreads();
    }

    const int lrow = lane>>2, lcol = (lane&3)*2;
#pragma unroll
    for (int mi=0;mi<4;mi++){
#pragma unroll
        for (int ni=0;ni<8;ni++){
            int cw = wn*64 + ni*8 + lcol;
            int n  = n0 + cw;
#pragma unroll
            for (int half=0; half<2; half++){
                int m = m0 + wm*64 + mi*16 + lrow + half*8;
                float v0 = acc[mi][ni][2*half], v1 = acc[mi][ni][2*half+1];
                if (MODE==0){
                    int b = m>>11, t = m&(TT-1), h = blockIdx.x, d = cw;
                    if (z==0){
                        v0 *= 0.08838834764831845f; v1 *= 0.08838834764831845f;
                        size_t o = ((size_t)(b*NH+h)*TT + t)*HD + d;
                        *(f162*)&g_qh[o] = __halves2half2(__float2half(v0), __float2half(v1));
                    } else if (z==1){
                        size_t o = ((size_t)(b*NH+h)*TT + t)*HD + d;
                        *(f162*)&g_kh[o] = __halves2half2(__float2half(v0), __float2half(v1));
                    } else {
                        size_t o = ((size_t)(b*NH+h)*HD + d)*TT + t;
                        g_vth[o] = __float2half(v0);
                        g_vth[o+TT] = __float2half(v1);
                    }
                } else {
                    *(float2*)&outf[(size_t)m*CC + n] = make_float2(v0, v1);
                }
            }
        }
    }
}

// ---- fused flash attention: 64q x 64k tiles, 4 warps ----
// S = Qh*Kh 1-pass; PV = Ph*Vh 1-pass.
#define SKQ 136
#define SKV 72
#define FQH 0
#define FKH (64*SKQ*2)
#define FVH (2*64*SKQ*2)
#define FS_SMEM (2*64*SKQ*2 + 128*SKV*2)   // 53248

__global__ __launch_bounds__(128, 3) void flash_k()
{
    extern __shared__ f16 fsm[];
    uint32_t sb = su32(fsm);
    const uint32_t QH=sb+FQH, KH=sb+FKH, VH=sb+FVH;
    const int tid = threadIdx.x, wid = tid>>5, lane = tid&31;
    const int bh = blockIdx.y, q0 = blockIdx.x*64;

    const f16* Qh = g_qh + ((size_t)bh*TT + q0)*HD;
    const f16* Kh = g_kh + (size_t)bh*TT*HD;
    const f16* Vh = g_vth + (size_t)bh*HD*TT;

    auto ldQK = [&](uint32_t dst, const f16* src){
#pragma unroll
        for (int j=0;j<8;j++){
            int lin = j*128+tid, row = lin>>4, c = lin&15;
            CP_ASYNC16(dst + row*(SKQ*2) + c*16, src + (size_t)row*HD + c*8);
        }
    };
    auto ldV = [&](uint32_t dst, const f16* src, int coloff){
#pragma unroll
        for (int j=0;j<8;j++){
            int lin = j*128+tid, row = lin>>3, c = lin&7;
            CP_ASYNC16(dst + row*(SKV*2) + c*16, src + (size_t)row*TT + coloff + c*8);
        }
    };

    ldQK(QH, Qh);
    CP_COMMIT();

    float acc[16][4];
#pragma unroll
    for (int j=0;j<16;j++){ acc[j][0]=0;acc[j][1]=0;acc[j][2]=0;acc[j][3]=0; }
    float m0=-1e30f, m1=-1e30f, l0=0.0f, l1=0.0f;

    for (int kt=0; kt<TT/64; kt++){
        __syncthreads();
        ldQK(KH, Kh + (size_t)kt*64*HD);
        ldV(VH, Vh, kt*64);
        CP_COMMIT();
        asm volatile("cp.async.wait_group 0;":::"memory");
        __syncthreads();

        // ---- S = QK^T (1-pass) ----
        float S[8][4];
#pragma unroll
        for (int j=0;j<8;j++){ S[j][0]=0;S[j][1]=0;S[j][2]=0;S[j][3]=0; }
#pragma unroll
        for (int ks=0;ks<8;ks++){
            uint32_t qh[4];
            int ar = wid*16 + (lane&15);
            uint32_t acol = (ks*16 + ((lane>>4)<<3))*2;
            LDSM4(qh[0],qh[1],qh[2],qh[3], QH + ar*(SKQ*2) + acol);
#pragma unroll
            for (int g=0;g<4;g++){
                int nr = g*16 + ((lane>>4)<<3) + (lane&7);
                uint32_t bcol = (ks*16 + ((lane>>3)&1)*8)*2;
                uint32_t h0,h1,h2,h3;
                LDSM4(h0,h1,h2,h3, KH + nr*(SKQ*2) + bcol);
                uint32_t bh0[2]={h0,h1}, bh1[2]={h2,h3};
                mma16816(S[2*g],   qh, bh0); mma16816(S[2*g+1], qh, bh1);
            }
        }

        // ---- online softmax ----
        float mx0=-1e30f, mx1=-1e30f;
#pragma unroll
        for (int j=0;j<8;j++){
            mx0 = fmaxf(mx0, fmaxf(S[j][0],S[j][1]));
            mx1 = fmaxf(mx1, fmaxf(S[j][2],S[j][3]));
        }
        mx0 = fmaxf(mx0, __shfl_xor_sync(~0u,mx0,1)); mx0 = fmaxf(mx0, __shfl_xor_sync(~0u,mx0,2));
        mx1 = fmaxf(mx1, __shfl_xor_sync(~0u,mx1,1)); mx1 = fmaxf(mx1, __shfl_xor_sync(~0u,mx1,2));
        float mn0 = fmaxf(m0,mx0), mn1 = fmaxf(m1,mx1);
        float c0 = __expf(m0-mn0), c1 = __expf(m1-mn1);
        float ls0=0.0f, ls1=0.0f;
#pragma unroll
        for (int j=0;j<8;j++){
            S[j][0]=__expf(S[j][0]-mn0); S[j][1]=__expf(S[j][1]-mn0); ls0 += S[j][0]+S[j][1];
            S[j][2]=__expf(S[j][2]-mn1); S[j][3]=__expf(S[j][3]-mn1); ls1 += S[j][2]+S[j][3];
        }
        ls0 += __shfl_xor_sync(~0u,ls0,1); ls0 += __shfl_xor_sync(~0u,ls0,2);
        ls1 += __shfl_xor_sync(~0u,ls1,1); ls1 += __shfl_xor_sync(~0u,ls1,2);
        l0 = l0*c0 + ls0; l1 = l1*c1 + ls1; m0 = mn0; m1 = mn1;
#pragma unroll
        for (int j=0;j<16;j++){ acc[j][0]*=c0; acc[j][1]*=c0; acc[j][2]*=c1; acc[j][3]*=c1; }

        // ---- acc += P V (1-pass) ----
#pragma unroll
        for (int ks=0;ks<4;ks++){
            uint32_t ph[4];
            ph[0]=pack2(S[2*ks][0],  S[2*ks][1]);   ph[1]=pack2(S[2*ks][2],  S[2*ks][3]);
            ph[2]=pack2(S[2*ks+1][0],S[2*ks+1][1]); ph[3]=pack2(S[2*ks+1][2],S[2*ks+1][3]);
#pragma unroll
            for (int g=0;g<8;g++){
                int nr = g*16 + ((lane>>4)<<3) + (lane&7);
                uint32_t bcol = (ks*16 + ((lane>>3)&1)*8)*2;
                uint32_t h0,h1,h2,h3;
                LDSM4(h0,h1,h2,h3, VH + nr*(SKV*2) + bcol);
                uint32_t bh0[2]={h0,h1}, bh1[2]={h2,h3};
                mma16816(acc[2*g],   ph, bh0); mma16816(acc[2*g+1], ph, bh1);
            }
        }
    }

    // ---- write y (fp16) in [B,T,C] ----
    float i0 = 1.0f/l0, i1 = 1.0f/l1;
    int b = bh>>4, h = bh&15;
    int t0 = q0 + wid*16 + (lane>>2);
#pragma unroll
    for (int j=0;j<16;j++){
        int d = j*8 + (lane&3)*2;
        {
            size_t o = ((size_t)(b*TT + t0))*CC + h*HD + d;
            *(f162*)&g_yh[o] = __halves2half2(__float2half(acc[j][0]*i0), __float2half(acc[j][1]*i0));
        }
        {
            size_t o = ((size_t)(b*TT + t0 + 8))*CC + h*HD + d;
            *(f162*)&g_yh[o] = __halves2half2(__float2half(acc[j][2]*i1), __float2half(acc[j][3]*i1));
        }
    }
}

// ---- launch ----
extern "C" void kernel_launch(void* const* d_in, const int* in_sizes, int n_in,
                              void* d_out, int out_size)
{
    const float* x  = (const float*)d_in[0];
    const float* wq = (const float*)d_in[1];
    const float* wk = (const float*)d_in[2];
    const float* wv = (const float*)d_in[3];
    const float* wo = (const float*)d_in[4];
    float* out = (float*)d_out;

    cudaFuncSetAttribute(tc_gemm<0>, cudaFuncAttributeMaxDynamicSharedMemorySize, SMEM_DYN);
    cudaFuncSetAttribute(tc_gemm<1>, cudaFuncAttributeMaxDynamicSharedMemorySize, SMEM_DYN);
    cudaFuncSetAttribute(flash_k,   cudaFuncAttributeMaxDynamicSharedMemorySize, FS_SMEM);

    split_x<<<MTOT*CC/1024, 256>>>(x);
    split_w<<<dim3(CC*CC/1024, 4), 256>>>(wq, wk, wv, wo);

    tc_gemm<0><<<dim3(16,32,3), 128, SMEM_DYN>>>(nullptr);  // Q,K,V^T
    flash_k<<<dim3(TT/64, BHH), 128, FS_SMEM>>>();           // attention -> y fp16
    tc_gemm<1><<<dim3(16,32), 128, SMEM_DYN>>>(out);         // out-proj
}

// round 16
// speedup vs baseline: 3.2430x; 1.1671x over previous
#include <cuda_runtime.h>
#include <cuda_fp16.h>
#include <cstdint>

#define BD 2
#define TT 2048
#define CC 2048
#define NH 16
#define HD 128
#define MTOT (BD*TT)
#define BHH (BD*NH)
typedef __half f16;
typedef __half2 f162;

__device__ f16 g_xh[MTOT*CC];
__device__ f16 g_wh[4][CC*CC];     // wq (pre-scaled), wk, wv, wo — hi only
__device__ f16 g_qh[BHH*TT*HD];
__device__ f16 g_kh[BHH*TT*HD];
__device__ f16 g_vth[BHH*HD*TT];
__device__ f16 g_yh[MTOT*CC];

// ---- helpers ----
__device__ __forceinline__ uint32_t su32(const void* p){
    uint32_t a; asm("{.reg .u64 t; cvta.to.shared.u64 t,%1; cvt.u32.u64 %0,t;}":"=r"(a):"l"(p)); return a;
}
#define CP_ASYNC16(s,g) asm volatile("cp.async.cg.shared.global [%0], [%1], 16;" ::"r"(s),"l"(g))
#define CP_COMMIT() asm volatile("cp.async.commit_group;" ::: "memory")
#define LDSM4(r0,r1,r2,r3,addr) \
    asm volatile("ldmatrix.sync.aligned.m8n8.x4.shared.b16 {%0,%1,%2,%3},[%4];" \
                 :"=r"(r0),"=r"(r1),"=r"(r2),"=r"(r3):"r"(addr))

__device__ __forceinline__ void mma16816(float* d, const uint32_t* a, const uint32_t* b){
    asm volatile("mma.sync.aligned.m16n8k16.row.col.f32.f16.f16.f32 "
        "{%0,%1,%2,%3},{%4,%5,%6,%7},{%8,%9},{%0,%1,%2,%3};"
        : "+f"(d[0]),"+f"(d[1]),"+f"(d[2]),"+f"(d[3])
        : "r"(a[0]),"r"(a[1]),"r"(a[2]),"r"(a[3]),"r"(b[0]),"r"(b[1]));
}

__device__ __forceinline__ uint32_t pack2(float x, float y){
    f162 t = __halves2half2(__float2half(x), __float2half(y));
    return *(uint32_t*)&t;
}

// ---- conversions (fp32 -> fp16; wq pre-scaled by 1/sqrt(HD)) ----
__global__ __launch_bounds__(256) void split_x(const float* __restrict__ s){
    int i = blockIdx.x*256 + threadIdx.x;
    float4 v = ((const float4*)s)[i];
    ((f162*)g_xh)[2*i  ] = __halves2half2(__float2half(v.x), __float2half(v.y));
    ((f162*)g_xh)[2*i+1] = __halves2half2(__float2half(v.z), __float2half(v.w));
}
__global__ __launch_bounds__(256) void split_w(const float* __restrict__ w0,
                                               const float* __restrict__ w1,
                                               const float* __restrict__ w2,
                                               const float* __restrict__ w3){
    int wi = blockIdx.y;
    const float* s = (wi==0)?w0:(wi==1)?w1:(wi==2)?w2:w3;
    float sc = (wi==0) ? 0.08838834764831845f : 1.0f;
    int i = blockIdx.x*256 + threadIdx.x;
    float4 v = ((const float4*)s)[i];
    ((f162*)g_wh[wi])[2*i  ] = __halves2half2(__float2half(v.x*sc), __float2half(v.y*sc));
    ((f162*)g_wh[wi])[2*i+1] = __halves2half2(__float2half(v.z*sc), __float2half(v.w*sc));
}

// ---- warp-MMA GEMM: 128x128 tile, 4 warps (64x64), BK=64, all 1-pass ----
// MODE 0: QKV (z: 0=Q, 1=K, 2=V^T). MODE 1: out-proj.
#define BK 64
#define AS 72
#define TILE_B (128*AS*2)
#define SMEM_DYN (4*TILE_B)

template<int MODE>
__global__ __launch_bounds__(128, 2) void tc_gemm(float* __restrict__ outf)
{
    extern __shared__ f16 smem[];
    uint32_t sb = su32(smem);
    const int tid = threadIdx.x, wid = tid>>5, lane = tid&31;
    const int wm = wid&1, wn = wid>>1;
    const int n0 = blockIdx.x*128, m0 = blockIdx.y*128, z = blockIdx.z;

    const f16 *Ah,*Bh;
    if (MODE==0){ Ah=g_xh; Bh=g_wh[z]; }
    else        { Ah=g_yh; Bh=g_wh[3]; }
    const int K = CC, NC = K/BK;

    auto load_chunk = [&](int c, int b){
        int kk = c*BK;
        uint32_t sa = sb + b*TILE_B;
        uint32_t sB = sb + 2*TILE_B + b*TILE_B;
#pragma unroll
        for (int j=0;j<8;j++){
            int lin = j*128+tid, row = lin>>3, c16 = lin&7;
            CP_ASYNC16(sa + row*(AS*2) + c16*16, Ah + (size_t)(m0+row)*K + kk + c16*8);
        }
#pragma unroll
        for (int j=0;j<8;j++){
            int lin = j*128+tid, row = lin>>3, c16 = lin&7;
            CP_ASYNC16(sB + row*(AS*2) + c16*16, Bh + (size_t)(n0+row)*K + kk + c16*8);
        }
        CP_COMMIT();
    };

    float acc[4][8][4];
#pragma unroll
    for (int mi=0;mi<4;mi++)
#pragma unroll
        for (int ni=0;ni<8;ni++)
#pragma unroll
            for (int r=0;r<4;r++) acc[mi][ni][r] = 0.0f;

    load_chunk(0,0);
    for (int c=0;c<NC;c++){
        if (c+1<NC){ load_chunk(c+1,(c+1)&1); asm volatile("cp.async.wait_group 1;":::"memory"); }
        else asm volatile("cp.async.wait_group 0;":::"memory");
        __syncthreads();
        uint32_t sa = sb + (c&1)*TILE_B;
        uint32_t sB = sb + 2*TILE_B + (c&1)*TILE_B;
#pragma unroll
        for (int ks=0;ks<BK;ks+=16){
            uint32_t af[4][4], bfr[8][2];
#pragma unroll
            for (int mi=0;mi<4;mi++){
                int r = wm*64 + mi*16 + (lane&15);
                uint32_t addr = sa + r*(AS*2) + (ks + ((lane>>4)<<3))*2;
                LDSM4(af[mi][0],af[mi][1],af[mi][2],af[mi][3], addr);
            }
#pragma unroll
            for (int g=0;g<4;g++){
                int nr = wn*64 + g*16 + ((lane>>4)<<3) + (lane&7);
                uint32_t addr = sB + nr*(AS*2) + (ks + ((lane>>3)&1)*8)*2;
                uint32_t r0,r1,r2,r3;
                LDSM4(r0,r1,r2,r3, addr);
                bfr[2*g][0]=r0; bfr[2*g][1]=r1; bfr[2*g+1][0]=r2; bfr[2*g+1][1]=r3;
            }
#pragma unroll
            for (int mi=0;mi<4;mi++)
#pragma unroll
                for (int ni=0;ni<8;ni++)
                    mma16816(acc[mi][ni], af[mi], bfr[ni]);
        }
        __syncthreads();
    }

    const int lrow = lane>>2, lcol = (lane&3)*2;
#pragma unroll
    for (int mi=0;mi<4;mi++){
#pragma unroll
        for (int ni=0;ni<8;ni++){
            int cw = wn*64 + ni*8 + lcol;
            int n  = n0 + cw;
#pragma unroll
            for (int half=0; half<2; half++){
                int m = m0 + wm*64 + mi*16 + lrow + half*8;
                float v0 = acc[mi][ni][2*half], v1 = acc[mi][ni][2*half+1];
                if (MODE==0){
                    int b = m>>11, t = m&(TT-1), h = blockIdx.x, d = cw;
                    if (z==2){
                        size_t o = ((size_t)(b*NH+h)*HD + d)*TT + t;
                        g_vth[o] = __float2half(v0);
                        g_vth[o+TT] = __float2half(v1);
                    } else {
                        f16* dst = (z==0) ? g_qh : g_kh;
                        size_t o = ((size_t)(b*NH+h)*TT + t)*HD + d;
                        *(f162*)&dst[o] = __halves2half2(__float2half(v0), __float2half(v1));
                    }
                } else {
                    *(float2*)&outf[(size_t)m*CC + n] = make_float2(v0, v1);
                }
            }
        }
    }
}

// ---- fused flash attention: 64q x 64k tiles, 4 warps, 3 CTAs/SM ----
#define SKQ 136
#define SKV 72
#define FQH 0
#define FKH (64*SKQ*2)
#define FVH (2*64*SKQ*2)
#define FS_SMEM (2*64*SKQ*2 + 128*SKV*2)   // 53248

__global__ __launch_bounds__(128, 3) void flash_k()
{
    extern __shared__ f16 fsm[];
    uint32_t sb = su32(fsm);
    const uint32_t QH=sb+FQH, KH=sb+FKH, VH=sb+FVH;
    const int tid = threadIdx.x, wid = tid>>5, lane = tid&31;
    const int bh = blockIdx.y, q0 = blockIdx.x*64;

    const f16* Qh = g_qh + ((size_t)bh*TT + q0)*HD;
    const f16* Kh = g_kh + (size_t)bh*TT*HD;
    const f16* Vh = g_vth + (size_t)bh*HD*TT;

    auto ldQK = [&](uint32_t dst, const f16* src){
#pragma unroll
        for (int j=0;j<8;j++){
            int lin = j*128+tid, row = lin>>4, c = lin&15;
            CP_ASYNC16(dst + row*(SKQ*2) + c*16, src + (size_t)row*HD + c*8);
        }
    };
    auto ldV = [&](uint32_t dst, const f16* src, int coloff){
#pragma unroll
        for (int j=0;j<8;j++){
            int lin = j*128+tid, row = lin>>3, c = lin&7;
            CP_ASYNC16(dst + row*(SKV*2) + c*16, src + (size_t)row*TT + coloff + c*8);
        }
    };

    ldQK(QH, Qh);
    CP_COMMIT();

    float acc[16][4];
#pragma unroll
    for (int j=0;j<16;j++){ acc[j][0]=0;acc[j][1]=0;acc[j][2]=0;acc[j][3]=0; }
    float m0=-1e30f, m1=-1e30f, l0=0.0f, l1=0.0f;

    for (int kt=0; kt<TT/64; kt++){
        __syncthreads();
        ldQK(KH, Kh + (size_t)kt*64*HD);
        ldV(VH, Vh, kt*64);
        CP_COMMIT();
        asm volatile("cp.async.wait_group 0;":::"memory");
        __syncthreads();

        // ---- S = QK^T (1-pass) ----
        float S[8][4];
#pragma unroll
        for (int j=0;j<8;j++){ S[j][0]=0;S[j][1]=0;S[j][2]=0;S[j][3]=0; }
#pragma unroll
        for (int ks=0;ks<8;ks++){
            uint32_t qh[4];
            int ar = wid*16 + (lane&15);
            uint32_t acol = (ks*16 + ((lane>>4)<<3))*2;
            LDSM4(qh[0],qh[1],qh[2],qh[3], QH + ar*(SKQ*2) + acol);
#pragma unroll
            for (int g=0;g<4;g++){
                int nr = g*16 + ((lane>>4)<<3) + (lane&7);
                uint32_t bcol = (ks*16 + ((lane>>3)&1)*8)*2;
                uint32_t h0,h1,h2,h3;
                LDSM4(h0,h1,h2,h3, KH + nr*(SKQ*2) + bcol);
                uint32_t bh0[2]={h0,h1}, bh1[2]={h2,h3};
                mma16816(S[2*g],   qh, bh0); mma16816(S[2*g+1], qh, bh1);
            }
        }

        // ---- online softmax ----
        float mx0=-1e30f, mx1=-1e30f;
#pragma unroll
        for (int j=0;j<8;j++){
            mx0 = fmaxf(mx0, fmaxf(S[j][0],S[j][1]));
            mx1 = fmaxf(mx1, fmaxf(S[j][2],S[j][3]));
        }
        mx0 = fmaxf(mx0, __shfl_xor_sync(~0u,mx0,1)); mx0 = fmaxf(mx0, __shfl_xor_sync(~0u,mx0,2));
        mx1 = fmaxf(mx1, __shfl_xor_sync(~0u,mx1,1)); mx1 = fmaxf(mx1, __shfl_xor_sync(~0u,mx1,2));
        float mn0 = fmaxf(m0,mx0), mn1 = fmaxf(m1,mx1);
        float c0 = __expf(m0-mn0), c1 = __expf(m1-mn1);
        float ls0=0.0f, ls1=0.0f;
#pragma unroll
        for (int j=0;j<8;j++){
            S[j][0]=__expf(S[j][0]-mn0); S[j][1]=__expf(S[j][1]-mn0); ls0 += S[j][0]+S[j][1];
            S[j][2]=__expf(S[j][2]-mn1); S[j][3]=__expf(S[j][3]-mn1); ls1 += S[j][2]+S[j][3];
        }
        ls0 += __shfl_xor_sync(~0u,ls0,1); ls0 += __shfl_xor_sync(~0u,ls0,2);
        ls1 += __shfl_xor_sync(~0u,ls1,1); ls1 += __shfl_xor_sync(~0u,ls1,2);
        l0 = l0*c0 + ls0; l1 = l1*c1 + ls1; m0 = mn0; m1 = mn1;
#pragma unroll
        for (int j=0;j<16;j++){ acc[j][0]*=c0; acc[j][1]*=c0; acc[j][2]*=c1; acc[j][3]*=c1; }

        // ---- acc += P V (1-pass) ----
#pragma unroll
        for (int ks=0;ks<4;ks++){
            uint32_t ph[4];
            ph[0]=pack2(S[2*ks][0],  S[2*ks][1]);   ph[1]=pack2(S[2*ks][2],  S[2*ks][3]);
            ph[2]=pack2(S[2*ks+1][0],S[2*ks+1][1]); ph[3]=pack2(S[2*ks+1][2],S[2*ks+1][3]);
#pragma unroll
            for (int g=0;g<8;g++){
                int nr = g*16 + ((lane>>4)<<3) + (lane&7);
                uint32_t bcol = (ks*16 + ((lane>>3)&1)*8)*2;
                uint32_t h0,h1,h2,h3;
                LDSM4(h0,h1,h2,h3, VH + nr*(SKV*2) + bcol);
                uint32_t bh0[2]={h0,h1}, bh1[2]={h2,h3};
                mma16816(acc[2*g],   ph, bh0); mma16816(acc[2*g+1], ph, bh1);
            }
        }
    }

    // ---- write y (fp16) in [B,T,C] ----
    float i0 = 1.0f/l0, i1 = 1.0f/l1;
    int b = bh>>4, h = bh&15;
    int t0 = q0 + wid*16 + (lane>>2);
#pragma unroll
    for (int j=0;j<16;j++){
        int d = j*8 + (lane&3)*2;
        {
            size_t o = ((size_t)(b*TT + t0))*CC + h*HD + d;
            *(f162*)&g_yh[o] = __halves2half2(__float2half(acc[j][0]*i0), __float2half(acc[j][1]*i0));
        }
        {
            size_t o = ((size_t)(b*TT + t0 + 8))*CC + h*HD + d;
            *(f162*)&g_yh[o] = __halves2half2(__float2half(acc[j][2]*i1), __float2half(acc[j][3]*i1));
        }
    }
}

// ---- launch ----
extern "C" void kernel_launch(void* const* d_in, const int* in_sizes, int n_in,
                              void* d_out, int out_size)
{
    const float* x  = (const float*)d_in[0];
    const float* wq = (const float*)d_in[1];
    const float* wk = (const float*)d_in[2];
    const float* wv = (const float*)d_in[3];
    const float* wo = (const float*)d_in[4];
    float* out = (float*)d_out;

    cudaFuncSetAttribute(tc_gemm<0>, cudaFuncAttributeMaxDynamicSharedMemorySize, SMEM_DYN);
    cudaFuncSetAttribute(tc_gemm<1>, cudaFuncAttributeMaxDynamicSharedMemorySize, SMEM_DYN);
    cudaFuncSetAttribute(flash_k,   cudaFuncAttributeMaxDynamicSharedMemorySize, FS_SMEM);

    split_x<<<MTOT*CC/1024, 256>>>(x);
    split_w<<<dim3(CC*CC/1024, 4), 256>>>(wq, wk, wv, wo);

    tc_gemm<0><<<dim3(16,32,3), 128, SMEM_DYN>>>(nullptr);  // Q,K,V^T (1-pass each)
    flash_k<<<dim3(TT/64, BHH), 128, FS_SMEM>>>();           // attention -> y fp16
    tc_gemm<1><<<dim3(16,32), 128, SMEM_DYN>>>(out);         // out-proj
}